// round 1
// baseline (speedup 1.0000x reference)
#include <cuda_runtime.h>
#include <cuda_bf16.h>
#include <math.h>

// ---------------------------------------------------------------------------
// Problem constants: B=4, T=S=1024, D=1024, H=16, hd=64
// ---------------------------------------------------------------------------
#define BZ 4
#define TQ 1024
#define SK 1024
#define DM 1024
#define HH 16
#define HD 64

// ---------------------------------------------------------------------------
// Scratch (device globals; allocation-free, graph-capturable)
// ---------------------------------------------------------------------------
__device__ float g_de_in[BZ * TQ * DM];        // LN(decoder_input)
__device__ float g_qkv1 [BZ * TQ * 3 * DM];    // self-attn QKV
__device__ float g_scores[(long long)BZ * HH * TQ * SK]; // scores/probs (reused)
__device__ float g_ctx  [BZ * TQ * DM];        // attention context
__device__ float g_x    [BZ * TQ * DM];        // after self-attn residual
__device__ float g_enout[BZ * SK * DM];        // LN(encoder_output)
__device__ float g_q2   [BZ * TQ * DM];        // cross Q
__device__ float g_kv2  [BZ * SK * 2 * DM];    // cross K,V
__device__ float g_x2   [BZ * TQ * DM];        // after cross-attn residual
__device__ float g_tv   [BZ * SK * DM];        // en_out @ w_out2
__device__ float g_tvn  [BZ * SK];             // row norms of tv
__device__ float g_lnx  [BZ * TQ * DM];        // LN(x2)
__device__ float g_h    [BZ * TQ * 4 * DM];    // MLP hidden

// ---------------------------------------------------------------------------
// Block reductions (all blocks are 256 threads = 8 warps)
// ---------------------------------------------------------------------------
__device__ __forceinline__ float block_sum(float v, float* sh) {
#pragma unroll
    for (int o = 16; o > 0; o >>= 1) v += __shfl_xor_sync(0xffffffffu, v, o);
    if ((threadIdx.x & 31) == 0) sh[threadIdx.x >> 5] = v;
    __syncthreads();
    if (threadIdx.x < 32) {
        float w = (threadIdx.x < 8) ? sh[threadIdx.x] : 0.0f;
#pragma unroll
        for (int o = 4; o > 0; o >>= 1) w += __shfl_xor_sync(0xffffffffu, w, o);
        if (threadIdx.x == 0) sh[0] = w;
    }
    __syncthreads();
    float r = sh[0];
    __syncthreads();
    return r;
}

__device__ __forceinline__ float block_max(float v, float* sh) {
#pragma unroll
    for (int o = 16; o > 0; o >>= 1) v = fmaxf(v, __shfl_xor_sync(0xffffffffu, v, o));
    if ((threadIdx.x & 31) == 0) sh[threadIdx.x >> 5] = v;
    __syncthreads();
    if (threadIdx.x < 32) {
        float w = (threadIdx.x < 8) ? sh[threadIdx.x] : -3.4e38f;
#pragma unroll
        for (int o = 4; o > 0; o >>= 1) w = fmaxf(w, __shfl_xor_sync(0xffffffffu, w, o));
        if (threadIdx.x == 0) sh[0] = w;
    }
    __syncthreads();
    float r = sh[0];
    __syncthreads();
    return r;
}

// ---------------------------------------------------------------------------
// LayerNorm: one block per row of 1024, eps=1e-6
// ---------------------------------------------------------------------------
__global__ __launch_bounds__(256)
void ln_kernel(const float* __restrict__ x, float* __restrict__ y,
               const float* __restrict__ g, const float* __restrict__ beta)
{
    __shared__ float sh[32];
    const long long row = blockIdx.x;
    const float* xr = x + row * DM;
    float* yr = y + row * DM;
    const int tid = threadIdx.x;
    float v[4];
    float s = 0.f, sq = 0.f;
#pragma unroll
    for (int i = 0; i < 4; i++) {
        float t = xr[tid + 256 * i];
        v[i] = t; s += t; sq += t * t;
    }
    s  = block_sum(s, sh);
    sq = block_sum(sq, sh);
    float mean = s * (1.0f / 1024.0f);
    float var  = fmaxf(sq * (1.0f / 1024.0f) - mean * mean, 0.0f);
    float inv  = rsqrtf(var + 1e-6f);
#pragma unroll
    for (int i = 0; i < 4; i++) {
        int c = tid + 256 * i;
        yr[c] = (v[i] - mean) * inv * g[c] + beta[c];
    }
}

// ---------------------------------------------------------------------------
// Generic tiled GEMM.
//   C = alpha * A x op(B) (+bias[n]) (+gelu) (+res)
//   TRANSB=true : C[m,n] = sum_k A[m,k] * B[n,k]   (weights are [N,K] row-major)
//   TRANSB=false: C[m,n] = sum_k A[m,k] * B[k,n]
// Batched via blockIdx.z with (batch, head)-decomposed strides:
//   offset = (bz/nh)*Xb + (bz%nh)*Xh
// All problem dims divide the tiles; no bounds checks.
// ---------------------------------------------------------------------------
template<int BM, int BN, int BK, int TM, int TN, bool TRANSB, int ACT>
__global__ __launch_bounds__((BM / TM) * (BN / TN))
void gemm_kernel(const float* __restrict__ A, int lda, long long Ab, long long Ah,
                 const float* __restrict__ B, int ldb, long long Bb, long long Bh,
                 float* __restrict__ C, int ldc, long long Cb, long long Ch,
                 const float* __restrict__ bias,
                 const float* __restrict__ res, int ldr,
                 int M, int N, int K, float alpha, int nh)
{
    constexpr int THREADS = (BM / TM) * (BN / TN);
    __shared__ float As[BK][BM + 4];
    __shared__ float Bs[BK][BN + 4];

    const int bz = blockIdx.z;
    const int bb = bz / nh;
    const int hh = bz - bb * nh;
    A += bb * Ab + hh * Ah;
    B += bb * Bb + hh * Bh;
    C += bb * Cb + hh * Ch;

    const int m0 = blockIdx.y * BM;
    const int n0 = blockIdx.x * BN;
    const int t  = threadIdx.x;
    const int tx = t % (BN / TN);
    const int ty = t / (BN / TN);

    float acc[TM][TN];
#pragma unroll
    for (int i = 0; i < TM; i++)
#pragma unroll
        for (int j = 0; j < TN; j++) acc[i][j] = 0.0f;

    for (int k0 = 0; k0 < K; k0 += BK) {
        // A tile: BM x BK, stored transposed As[k][m]
#pragma unroll
        for (int u = 0; u < (BM * BK) / THREADS; u++) {
            int idx = t + u * THREADS;
            int r = idx / BK;
            int c = idx - r * BK;
            As[c][r] = A[(long long)(m0 + r) * lda + (k0 + c)];
        }
        // B tile
        if (TRANSB) {
#pragma unroll
            for (int u = 0; u < (BN * BK) / THREADS; u++) {
                int idx = t + u * THREADS;
                int r = idx / BK;
                int c = idx - r * BK;
                Bs[c][r] = B[(long long)(n0 + r) * ldb + (k0 + c)];
            }
        } else {
#pragma unroll
            for (int u = 0; u < (BN * BK) / THREADS; u++) {
                int idx = t + u * THREADS;
                int r = idx / BN;
                int c = idx - r * BN;
                Bs[r][c] = B[(long long)(k0 + r) * ldb + (n0 + c)];
            }
        }
        __syncthreads();

#pragma unroll
        for (int k = 0; k < BK; k++) {
            float av[TM], bv[TN];
#pragma unroll
            for (int i = 0; i < TM; i++) av[i] = As[k][ty * TM + i];
#pragma unroll
            for (int j = 0; j < TN; j++) bv[j] = Bs[k][tx * TN + j];
#pragma unroll
            for (int i = 0; i < TM; i++)
#pragma unroll
                for (int j = 0; j < TN; j++)
                    acc[i][j] = fmaf(av[i], bv[j], acc[i][j]);
        }
        __syncthreads();
    }

#pragma unroll
    for (int i = 0; i < TM; i++) {
        int m = m0 + ty * TM + i;
#pragma unroll
        for (int j = 0; j < TN; j++) {
            int n = n0 + tx * TN + j;
            float v = acc[i][j] * alpha;
            if (bias) v += bias[n];
            if (ACT == 1) v = 0.5f * v * (1.0f + erff(v * 0.70710678118654752f));
            if (res) v += res[(long long)m * ldr + n];
            C[(long long)m * ldc + n] = v;
        }
    }
}

// ---------------------------------------------------------------------------
// Row softmax over S=1024 with causal + key-padding mask.
// grid = (T, H, B), block = 256. In-place on scores.
// ---------------------------------------------------------------------------
__global__ __launch_bounds__(256)
void softmax_kernel(float* __restrict__ sc, const unsigned char* __restrict__ kpm,
                    int causal)
{
    __shared__ float sh[32];
    const int t = blockIdx.x, h = blockIdx.y, b = blockIdx.z;
    float* row = sc + (((long long)(b * HH + h)) * TQ + t) * SK;
    const unsigned char* kp = kpm + (long long)b * SK;
    const int tid = threadIdx.x;

    float v[4];
    float mx = -3.4e38f;
#pragma unroll
    for (int i = 0; i < 4; i++) {
        int s = tid + 256 * i;
        float x = row[s];
        if (causal && s > t) x -= 1e9f;
        if (kp[s]) x = -1e9f;
        v[i] = x;
        mx = fmaxf(mx, x);
    }
    mx = block_max(mx, sh);
    float sum = 0.f;
#pragma unroll
    for (int i = 0; i < 4; i++) {
        v[i] = __expf(v[i] - mx);
        sum += v[i];
    }
    sum = block_sum(sum, sh);
    float inv = 1.0f / sum;
#pragma unroll
    for (int i = 0; i < 4; i++) row[tid + 256 * i] = v[i] * inv;
}

// ---------------------------------------------------------------------------
// Row L2 norm over 1024 elements (for tv)
// ---------------------------------------------------------------------------
__global__ __launch_bounds__(256)
void rownorm_kernel(const float* __restrict__ x, float* __restrict__ out)
{
    __shared__ float sh[32];
    const long long row = blockIdx.x;
    const float* xr = x + row * DM;
    float sq = 0.f;
#pragma unroll
    for (int i = 0; i < 4; i++) {
        float t = xr[threadIdx.x + 256 * i];
        sq += t * t;
    }
    sq = block_sum(sq, sh);
    if (threadIdx.x == 0) out[row] = sqrtf(sq);
}

// ---------------------------------------------------------------------------
// wvn[b,t,s] = tvnorm[b,s] * (1/H) * sum_h probs[b,h,t,s]
// ---------------------------------------------------------------------------
__global__ __launch_bounds__(256)
void wvn_kernel(const float* __restrict__ probs, const float* __restrict__ tvn,
                float* __restrict__ out)
{
    long long i = (long long)blockIdx.x * blockDim.x + threadIdx.x;
    if (i >= (long long)BZ * TQ * SK) return;
    int s = (int)(i & 1023);
    long long bt = i >> 10;
    int t = (int)(bt & 1023);
    int b = (int)(bt >> 10);
    const float* p = probs + (long long)b * HH * TQ * SK + (long long)t * SK + s;
    float acc = 0.f;
#pragma unroll
    for (int h = 0; h < HH; h++) acc += p[(long long)h * TQ * SK];
    out[i] = acc * (1.0f / (float)HH) * tvn[b * SK + s];
}

// ---------------------------------------------------------------------------
// Host launcher
// ---------------------------------------------------------------------------
extern "C" void kernel_launch(void* const* d_in, const int* in_sizes, int n_in,
                              void* d_out, int out_size)
{
    const float* dec_in  = (const float*)d_in[0];
    const float* enc_out = (const float*)d_in[1];
    const unsigned char* en_mask = (const unsigned char*)d_in[2];
    const unsigned char* de_mask = (const unsigned char*)d_in[3];
    const float* ln_g   = (const float*)d_in[4];
    const float* ln_b   = (const float*)d_in[5];
    const float* w_in1  = (const float*)d_in[6];
    const float* b_in1  = (const float*)d_in[7];
    const float* w_out1 = (const float*)d_in[8];
    const float* b_out1 = (const float*)d_in[9];
    const float* w_in2  = (const float*)d_in[10];
    const float* b_in2  = (const float*)d_in[11];
    const float* w_out2 = (const float*)d_in[12];
    const float* b_out2 = (const float*)d_in[13];
    const float* mlp_w1 = (const float*)d_in[14];
    const float* mlp_b1 = (const float*)d_in[15];
    const float* mlp_w2 = (const float*)d_in[16];
    const float* mlp_b2 = (const float*)d_in[17];

    float *de_in, *qkv1, *scores, *ctx, *x, *enout, *q2, *kv2, *x2, *tv, *tvn, *lnx, *hbuf;
    cudaGetSymbolAddress((void**)&de_in,  g_de_in);
    cudaGetSymbolAddress((void**)&qkv1,   g_qkv1);
    cudaGetSymbolAddress((void**)&scores, g_scores);
    cudaGetSymbolAddress((void**)&ctx,    g_ctx);
    cudaGetSymbolAddress((void**)&x,      g_x);
    cudaGetSymbolAddress((void**)&enout,  g_enout);
    cudaGetSymbolAddress((void**)&q2,     g_q2);
    cudaGetSymbolAddress((void**)&kv2,    g_kv2);
    cudaGetSymbolAddress((void**)&x2,     g_x2);
    cudaGetSymbolAddress((void**)&tv,     g_tv);
    cudaGetSymbolAddress((void**)&tvn,    g_tvn);
    cudaGetSymbolAddress((void**)&lnx,    g_lnx);
    cudaGetSymbolAddress((void**)&hbuf,   g_h);

    float* out1 = (float*)d_out;                       // [B,T,D]
    float* out2 = (float*)d_out + (long long)BZ * TQ * DM; // [B,T,S]

    const int BT = BZ * TQ; // 4096 rows
    const long long TSh = (long long)TQ * SK;          // per-head score stride
    const long long TSb = (long long)HH * TQ * SK;     // per-batch score stride

    // 1-2: LayerNorms of the two stream inputs
    ln_kernel<<<BT, 256>>>(dec_in, de_in, ln_g, ln_b);
    ln_kernel<<<BT, 256>>>(enc_out, enout, ln_g, ln_b);

    // 3: QKV1 = de_in @ w_in1^T + b_in1   [4096 x 3072]
    gemm_kernel<128,128,16,8,8,true,0><<<dim3(3*DM/128, BT/128, 1), 256>>>(
        de_in, DM, 0, 0,  w_in1, DM, 0, 0,  qkv1, 3*DM, 0, 0,
        b_in1, nullptr, 0, BT, 3*DM, DM, 1.0f, 1);

    // 4: self-attn scores = 0.125 * Q @ K^T  (batched over 64 = B*H)
    gemm_kernel<128,128,16,8,8,true,0><<<dim3(SK/128, TQ/128, BZ*HH), 256>>>(
        qkv1,        3*DM, (long long)TQ*3*DM, HD,
        qkv1 + DM,   3*DM, (long long)SK*3*DM, HD,
        scores, SK, TSb, TSh,
        nullptr, nullptr, 0, TQ, SK, HD, 0.125f, HH);

    // 5: causal softmax with de_mask
    softmax_kernel<<<dim3(TQ, HH, BZ), 256>>>(scores, de_mask, 1);

    // 6: ctx = probs @ V   (batched NN, N=64)
    gemm_kernel<64,64,16,4,4,false,0><<<dim3(1, TQ/64, BZ*HH), 256>>>(
        scores, SK, TSb, TSh,
        qkv1 + 2*DM, 3*DM, (long long)SK*3*DM, HD,
        ctx, DM, (long long)TQ*DM, HD,
        nullptr, nullptr, 0, TQ, HD, SK, 1.0f, HH);

    // 7: x = decoder_input + ctx @ w_out1^T + b_out1
    gemm_kernel<128,128,16,8,8,true,0><<<dim3(DM/128, BT/128, 1), 256>>>(
        ctx, DM, 0, 0,  w_out1, DM, 0, 0,  x, DM, 0, 0,
        b_out1, dec_in, DM, BT, DM, DM, 1.0f, 1);

    // 8: q2 = x @ wq2^T + bq2
    gemm_kernel<128,128,16,8,8,true,0><<<dim3(DM/128, BT/128, 1), 256>>>(
        x, DM, 0, 0,  w_in2, DM, 0, 0,  q2, DM, 0, 0,
        b_in2, nullptr, 0, BT, DM, DM, 1.0f, 1);

    // 9: kv2 = en_out @ w_kv2^T + b_kv2   [4096 x 2048]
    gemm_kernel<128,128,16,8,8,true,0><<<dim3(2*DM/128, BT/128, 1), 256>>>(
        enout, DM, 0, 0,  w_in2 + (long long)DM*DM, DM, 0, 0,  kv2, 2*DM, 0, 0,
        b_in2 + DM, nullptr, 0, BT, 2*DM, DM, 1.0f, 1);

    // 10: cross-attn scores
    gemm_kernel<128,128,16,8,8,true,0><<<dim3(SK/128, TQ/128, BZ*HH), 256>>>(
        q2,  DM,   (long long)TQ*DM,   HD,
        kv2, 2*DM, (long long)SK*2*DM, HD,
        scores, SK, TSb, TSh,
        nullptr, nullptr, 0, TQ, SK, HD, 0.125f, HH);

    // 11: softmax with en_mask (no causal)
    softmax_kernel<<<dim3(TQ, HH, BZ), 256>>>(scores, en_mask, 0);

    // 12: ctx = probs2 @ V2
    gemm_kernel<64,64,16,4,4,false,0><<<dim3(1, TQ/64, BZ*HH), 256>>>(
        scores, SK, TSb, TSh,
        kv2 + DM, 2*DM, (long long)SK*2*DM, HD,
        ctx, DM, (long long)TQ*DM, HD,
        nullptr, nullptr, 0, TQ, HD, SK, 1.0f, HH);

    // 13: x2 = x + ctx @ w_out2^T + b_out2
    gemm_kernel<128,128,16,8,8,true,0><<<dim3(DM/128, BT/128, 1), 256>>>(
        ctx, DM, 0, 0,  w_out2, DM, 0, 0,  x2, DM, 0, 0,
        b_out2, x, DM, BT, DM, DM, 1.0f, 1);

    // 14: tv = en_out @ w_out2  (NOT transposed)
    gemm_kernel<128,128,16,8,8,false,0><<<dim3(DM/128, BT/128, 1), 256>>>(
        enout, DM, 0, 0,  w_out2, DM, 0, 0,  tv, DM, 0, 0,
        nullptr, nullptr, 0, BT, DM, DM, 1.0f, 1);

    // 15: tvnorm = ||tv|| rows
    rownorm_kernel<<<BT, 256>>>(tv, tvn);

    // 16: wvn output (second output)
    {
        long long n = (long long)BZ * TQ * SK;
        wvn_kernel<<<(unsigned)((n + 255) / 256), 256>>>(scores, tvn, out2);
    }

    // 17: lnx = LN(x2)
    ln_kernel<<<BT, 256>>>(x2, lnx, ln_g, ln_b);

    // 18: h = gelu(lnx @ mlp_w1^T + mlp_b1)   [4096 x 4096]
    gemm_kernel<128,128,16,8,8,true,1><<<dim3(4*DM/128, BT/128, 1), 256>>>(
        lnx, DM, 0, 0,  mlp_w1, DM, 0, 0,  hbuf, 4*DM, 0, 0,
        mlp_b1, nullptr, 0, BT, 4*DM, DM, 1.0f, 1);

    // 19: out1 = x2 + h @ mlp_w2^T + mlp_b2
    gemm_kernel<128,128,16,8,8,true,0><<<dim3(DM/128, BT/128, 1), 256>>>(
        hbuf, 4*DM, 0, 0,  mlp_w2, 4*DM, 0, 0,  out1, DM, 0, 0,
        mlp_b2, x2, DM, BT, DM, 4*DM, 1.0f, 1);
}

// round 3
// speedup vs baseline: 2.0429x; 2.0429x over previous
#include <cuda_runtime.h>
#include <cuda_bf16.h>
#include <math.h>
#include <stdint.h>

// ---------------------------------------------------------------------------
// Problem constants: B=4, T=S=1024, D=1024, H=16, hd=64
// ---------------------------------------------------------------------------
#define BZ 4
#define TQ 1024
#define SK 1024
#define DM 1024
#define HH 16
#define HD 64

// ---------------------------------------------------------------------------
// Scratch (device globals; allocation-free, graph-capturable)
// ---------------------------------------------------------------------------
__device__ float g_de_in[BZ * TQ * DM];
__device__ float g_qkv1 [BZ * TQ * 3 * DM];
__device__ float g_scores[(long long)BZ * HH * TQ * SK];
__device__ float g_ctx  [BZ * TQ * DM];
__device__ float g_x    [BZ * TQ * DM];
__device__ float g_enout[BZ * SK * DM];
__device__ float g_q2   [BZ * TQ * DM];
__device__ float g_kv2  [BZ * SK * 2 * DM];
__device__ float g_x2   [BZ * TQ * DM];
__device__ float g_tv   [BZ * SK * DM];
__device__ float g_tvn  [BZ * SK];
__device__ float g_lnx  [BZ * TQ * DM];
__device__ float g_h    [BZ * TQ * 4 * DM];

// ---------------------------------------------------------------------------
// MMA / ldmatrix primitives (sm_80+; safe on plain sm_103 target)
// ---------------------------------------------------------------------------
__device__ __forceinline__ uint32_t smem_u32(const void* p) {
    uint32_t a;
    asm("{ .reg .u64 t; cvta.to.shared.u64 t, %1; cvt.u32.u64 %0, t; }" : "=r"(a) : "l"(p));
    return a;
}
__device__ __forceinline__ void ldsm_x4(uint32_t addr, uint32_t* r) {
    asm volatile("ldmatrix.sync.aligned.m8n8.x4.shared.b16 {%0,%1,%2,%3}, [%4];"
        : "=r"(r[0]), "=r"(r[1]), "=r"(r[2]), "=r"(r[3]) : "r"(addr));
}
__device__ __forceinline__ void mma_bf16(float* c, const uint32_t* a, const uint32_t* b) {
    asm volatile("mma.sync.aligned.m16n8k16.row.col.f32.bf16.bf16.f32 "
        "{%0,%1,%2,%3}, {%4,%5,%6,%7}, {%8,%9}, {%0,%1,%2,%3};"
        : "+f"(c[0]), "+f"(c[1]), "+f"(c[2]), "+f"(c[3])
        : "r"(a[0]), "r"(a[1]), "r"(a[2]), "r"(a[3]), "r"(b[0]), "r"(b[1]));
}
__device__ __forceinline__ void split_bf16(float f, unsigned short& h, unsigned short& l) {
    __nv_bfloat16 bh = __float2bfloat16(f);
    float fl = f - __bfloat162float(bh);
    __nv_bfloat16 bl = __float2bfloat16(fl);
    h = __bfloat16_as_ushort(bh);
    l = __bfloat16_as_ushort(bl);
}

// ---------------------------------------------------------------------------
// Tensor-core GEMM via mma.sync, bf16 3-term split (fp32-accurate).
//   C[M,N] = alpha * A @ op(B) (+bias[n]) (+gelu) (+res)
//   TRANSB=true : B stored [N,K];  false: B stored [K,N].
//   CTA tile 128 x BN, BK=32 fp32. 256 threads, 8 warps (4 m x 2 n).
//   Batched via blockIdx.z: offset = (z/nh)*Xb + (z%nh)*Xh.
// ---------------------------------------------------------------------------
template<int BN, bool TRANSB, int ACT>
__global__ __launch_bounds__(256, 1)
void mma_gemm(const float* __restrict__ A, int lda, long long Ab, long long Ah,
              const float* __restrict__ B, int ldb, long long Bb, long long Bh,
              float* __restrict__ C, int ldc, long long Cb, long long Ch,
              const float* __restrict__ bias,
              const float* __restrict__ res, int ldr,
              int K, float alpha, int nh)
{
    constexpr int PITCH = 40;               // halves per row (80 B, conflict-free)
    constexpr int ASZ = 128 * PITCH;        // halves per A sub-buffer
    constexpr int BSZ = BN * PITCH;
    constexpr int STAGE = 2 * ASZ + 2 * BSZ; // Ahi, Alo, Bhi, Blo
    constexpr int WN = BN / 2;              // warp tile n
    constexpr int NT = WN / 8;              // n-tiles (m16n8) per warp
    constexpr int NB4 = BN / 32;            // B float4 loads per thread
    constexpr int NC4 = BN / 4;             // for non-trans B indexing

    extern __shared__ __align__(128) unsigned short sm[];

    const int tid = threadIdx.x;
    const int lane = tid & 31;
    const int wid = tid >> 5;
    const int wm = (wid & 3) * 32;
    const int wn = (wid >> 2) * WN;

    const int bz = blockIdx.z;
    const int bb = bz / nh;
    const int hh = bz - bb * nh;
    const int m0 = blockIdx.y * 128;
    const int n0 = blockIdx.x * BN;

    const float* Ag = A + bb * Ab + hh * Ah + (long long)m0 * lda;
    const float* Bg = B + bb * Bb + hh * Bh + (TRANSB ? (long long)n0 * ldb : (long long)n0);
    float* Cg = C + bb * Cb + hh * Ch;

    float acc[2][NT][4];
#pragma unroll
    for (int mi = 0; mi < 2; mi++)
#pragma unroll
        for (int ni = 0; ni < NT; ni++)
#pragma unroll
            for (int j = 0; j < 4; j++) acc[mi][ni][j] = 0.0f;

    const uint32_t sb0 = smem_u32(sm);
    const int nk = K >> 5;

    float4 sa[4], sbv[NB4];

    // ---- prologue: stage k=0 ----
#pragma unroll
    for (int u = 0; u < 4; u++) {
        int idx = tid + u * 256;
        int row = idx >> 3, c4 = idx & 7;
        sa[u] = *(const float4*)(Ag + (long long)row * lda + c4 * 4);
    }
    if (TRANSB) {
#pragma unroll
        for (int u = 0; u < NB4; u++) {
            int idx = tid + u * 256;
            int row = idx >> 3, c4 = idx & 7;
            sbv[u] = *(const float4*)(Bg + (long long)row * ldb + c4 * 4);
        }
    } else {
#pragma unroll
        for (int u = 0; u < NB4; u++) {
            int idx = tid + u * 256;
            int kr = idx / NC4, nc4 = idx - kr * NC4;
            sbv[u] = *(const float4*)(Bg + (long long)kr * ldb + nc4 * 4);
        }
    }

    for (int k = 0; k < nk; k++) {
        const int buf = k & 1;
        unsigned short* sAhi = sm + buf * STAGE;
        unsigned short* sAlo = sAhi + ASZ;
        unsigned short* sBhi = sAlo + ASZ;
        unsigned short* sBlo = sBhi + BSZ;

        // ---- store staged regs -> smem (bf16 hi/lo split) ----
#pragma unroll
        for (int u = 0; u < 4; u++) {
            int idx = tid + u * 256;
            int row = idx >> 3, c4 = idx & 7;
            float4 v = sa[u];
            unsigned short h0,h1,h2,h3,l0,l1,l2,l3;
            split_bf16(v.x,h0,l0); split_bf16(v.y,h1,l1);
            split_bf16(v.z,h2,l2); split_bf16(v.w,h3,l3);
            int off = row * PITCH + c4 * 4;
            *(uint2*)(sAhi + off) = make_uint2((uint32_t)h0 | ((uint32_t)h1 << 16),
                                               (uint32_t)h2 | ((uint32_t)h3 << 16));
            *(uint2*)(sAlo + off) = make_uint2((uint32_t)l0 | ((uint32_t)l1 << 16),
                                               (uint32_t)l2 | ((uint32_t)l3 << 16));
        }
        if (TRANSB) {
#pragma unroll
            for (int u = 0; u < NB4; u++) {
                int idx = tid + u * 256;
                int row = idx >> 3, c4 = idx & 7;
                float4 v = sbv[u];
                unsigned short h0,h1,h2,h3,l0,l1,l2,l3;
                split_bf16(v.x,h0,l0); split_bf16(v.y,h1,l1);
                split_bf16(v.z,h2,l2); split_bf16(v.w,h3,l3);
                int off = row * PITCH + c4 * 4;
                *(uint2*)(sBhi + off) = make_uint2((uint32_t)h0 | ((uint32_t)h1 << 16),
                                                   (uint32_t)h2 | ((uint32_t)h3 << 16));
                *(uint2*)(sBlo + off) = make_uint2((uint32_t)l0 | ((uint32_t)l1 << 16),
                                                   (uint32_t)l2 | ((uint32_t)l3 << 16));
            }
        } else {
#pragma unroll
            for (int u = 0; u < NB4; u++) {
                int idx = tid + u * 256;
                int kr = idx / NC4, nc4 = idx - kr * NC4;
                float4 v = sbv[u];
                float f[4] = {v.x, v.y, v.z, v.w};
#pragma unroll
                for (int j = 0; j < 4; j++) {
                    unsigned short h, l;
                    split_bf16(f[j], h, l);
                    int off = (nc4 * 4 + j) * PITCH + kr;
                    sBhi[off] = h;
                    sBlo[off] = l;
                }
            }
        }
        __syncthreads();

        // ---- prefetch next chunk into regs ----
        if (k + 1 < nk) {
            int k0 = (k + 1) << 5;
#pragma unroll
            for (int u = 0; u < 4; u++) {
                int idx = tid + u * 256;
                int row = idx >> 3, c4 = idx & 7;
                sa[u] = *(const float4*)(Ag + (long long)row * lda + k0 + c4 * 4);
            }
            if (TRANSB) {
#pragma unroll
                for (int u = 0; u < NB4; u++) {
                    int idx = tid + u * 256;
                    int row = idx >> 3, c4 = idx & 7;
                    sbv[u] = *(const float4*)(Bg + (long long)row * ldb + k0 + c4 * 4);
                }
            } else {
#pragma unroll
                for (int u = 0; u < NB4; u++) {
                    int idx = tid + u * 256;
                    int kr = idx / NC4, nc4 = idx - kr * NC4;
                    sbv[u] = *(const float4*)(Bg + (long long)(k0 + kr) * ldb + nc4 * 4);
                }
            }
        }

        // ---- compute: 2 k-steps of 16 ----
        uint32_t base = sb0 + (uint32_t)buf * STAGE * 2;
#pragma unroll
        for (int kk = 0; kk < 32; kk += 16) {
            uint32_t ah[2][4], al[2][4];
            {
                int arow = wm + (lane & 15);
                int acol = kk + ((lane >> 4) << 3);
#pragma unroll
                for (int mi = 0; mi < 2; mi++) {
                    uint32_t ad = base + (uint32_t)(((arow + mi * 16) * PITCH + acol) * 2);
                    ldsm_x4(ad, ah[mi]);
                    ldsm_x4(ad + ASZ * 2, al[mi]);
                }
            }
            uint32_t bh[NT][2], bl[NT][2];
            {
                int brow = wn + (lane & 7) + ((lane & 16) >> 1);
                int bcol = kk + (((lane >> 3) & 1) << 3);
#pragma unroll
                for (int nj = 0; nj < NT / 2; nj++) {
                    uint32_t bd = base + (uint32_t)((2 * ASZ + (brow + nj * 16) * PITCH + bcol) * 2);
                    uint32_t r[4];
                    ldsm_x4(bd, r);
                    bh[2 * nj][0] = r[0]; bh[2 * nj][1] = r[1];
                    bh[2 * nj + 1][0] = r[2]; bh[2 * nj + 1][1] = r[3];
                    ldsm_x4(bd + BSZ * 2, r);
                    bl[2 * nj][0] = r[0]; bl[2 * nj][1] = r[1];
                    bl[2 * nj + 1][0] = r[2]; bl[2 * nj + 1][1] = r[3];
                }
            }
#pragma unroll
            for (int mi = 0; mi < 2; mi++)
#pragma unroll
                for (int ni = 0; ni < NT; ni++) {
                    mma_bf16(acc[mi][ni], ah[mi], bh[ni]);
                    mma_bf16(acc[mi][ni], ah[mi], bl[ni]);
                    mma_bf16(acc[mi][ni], al[mi], bh[ni]);
                }
        }
        __syncthreads();
    }

    // ---- epilogue ----
#pragma unroll
    for (int mi = 0; mi < 2; mi++) {
#pragma unroll
        for (int ni = 0; ni < NT; ni++) {
            int m = m0 + wm + mi * 16 + (lane >> 2);
            int n = n0 + wn + ni * 8 + (lane & 3) * 2;
#pragma unroll
            for (int rr = 0; rr < 2; rr++) {
                int mm = m + rr * 8;
                float v0 = acc[mi][ni][rr * 2 + 0] * alpha;
                float v1 = acc[mi][ni][rr * 2 + 1] * alpha;
                if (bias) { v0 += bias[n]; v1 += bias[n + 1]; }
                if (ACT == 1) {
                    v0 = 0.5f * v0 * (1.0f + erff(v0 * 0.70710678118654752f));
                    v1 = 0.5f * v1 * (1.0f + erff(v1 * 0.70710678118654752f));
                }
                if (res) {
                    v0 += res[(long long)mm * ldr + n];
                    v1 += res[(long long)mm * ldr + n + 1];
                }
                *(float2*)(Cg + (long long)mm * ldc + n) = make_float2(v0, v1);
            }
        }
    }
}

// ---------------------------------------------------------------------------
// Block reductions
// ---------------------------------------------------------------------------
__device__ __forceinline__ float block_sum(float v, float* sh) {
#pragma unroll
    for (int o = 16; o > 0; o >>= 1) v += __shfl_xor_sync(0xffffffffu, v, o);
    if ((threadIdx.x & 31) == 0) sh[threadIdx.x >> 5] = v;
    __syncthreads();
    if (threadIdx.x < 32) {
        float w = (threadIdx.x < 8) ? sh[threadIdx.x] : 0.0f;
#pragma unroll
        for (int o = 4; o > 0; o >>= 1) w += __shfl_xor_sync(0xffffffffu, w, o);
        if (threadIdx.x == 0) sh[0] = w;
    }
    __syncthreads();
    float r = sh[0];
    __syncthreads();
    return r;
}
__device__ __forceinline__ float block_max(float v, float* sh) {
#pragma unroll
    for (int o = 16; o > 0; o >>= 1) v = fmaxf(v, __shfl_xor_sync(0xffffffffu, v, o));
    if ((threadIdx.x & 31) == 0) sh[threadIdx.x >> 5] = v;
    __syncthreads();
    if (threadIdx.x < 32) {
        float w = (threadIdx.x < 8) ? sh[threadIdx.x] : -3.4e38f;
#pragma unroll
        for (int o = 4; o > 0; o >>= 1) w = fmaxf(w, __shfl_xor_sync(0xffffffffu, w, o));
        if (threadIdx.x == 0) sh[0] = w;
    }
    __syncthreads();
    float r = sh[0];
    __syncthreads();
    return r;
}

// ---------------------------------------------------------------------------
// LayerNorm / softmax / rownorm / wvn
// ---------------------------------------------------------------------------
__global__ __launch_bounds__(256)
void ln_kernel(const float* __restrict__ x, float* __restrict__ y,
               const float* __restrict__ g, const float* __restrict__ beta)
{
    __shared__ float sh[32];
    const long long row = blockIdx.x;
    const float* xr = x + row * DM;
    float* yr = y + row * DM;
    const int tid = threadIdx.x;
    float v[4];
    float s = 0.f, sq = 0.f;
#pragma unroll
    for (int i = 0; i < 4; i++) {
        float t = xr[tid + 256 * i];
        v[i] = t; s += t; sq += t * t;
    }
    s  = block_sum(s, sh);
    sq = block_sum(sq, sh);
    float mean = s * (1.0f / 1024.0f);
    float var  = fmaxf(sq * (1.0f / 1024.0f) - mean * mean, 0.0f);
    float inv  = rsqrtf(var + 1e-6f);
#pragma unroll
    for (int i = 0; i < 4; i++) {
        int c = tid + 256 * i;
        yr[c] = (v[i] - mean) * inv * g[c] + beta[c];
    }
}

__global__ __launch_bounds__(256)
void softmax_kernel(float* __restrict__ sc, const unsigned char* __restrict__ kpm,
                    int causal)
{
    __shared__ float sh[32];
    const int t = blockIdx.x, h = blockIdx.y, b = blockIdx.z;
    float* row = sc + (((long long)(b * HH + h)) * TQ + t) * SK;
    const unsigned char* kp = kpm + (long long)b * SK;
    const int tid = threadIdx.x;
    float v[4];
    float mx = -3.4e38f;
#pragma unroll
    for (int i = 0; i < 4; i++) {
        int s = tid + 256 * i;
        float x = row[s];
        if (causal && s > t) x -= 1e9f;
        if (kp[s]) x = -1e9f;
        v[i] = x;
        mx = fmaxf(mx, x);
    }
    mx = block_max(mx, sh);
    float sum = 0.f;
#pragma unroll
    for (int i = 0; i < 4; i++) {
        v[i] = __expf(v[i] - mx);
        sum += v[i];
    }
    sum = block_sum(sum, sh);
    float inv = 1.0f / sum;
#pragma unroll
    for (int i = 0; i < 4; i++) row[tid + 256 * i] = v[i] * inv;
}

__global__ __launch_bounds__(256)
void rownorm_kernel(const float* __restrict__ x, float* __restrict__ out)
{
    __shared__ float sh[32];
    const long long row = blockIdx.x;
    const float* xr = x + row * DM;
    float sq = 0.f;
#pragma unroll
    for (int i = 0; i < 4; i++) {
        float t = xr[threadIdx.x + 256 * i];
        sq += t * t;
    }
    sq = block_sum(sq, sh);
    if (threadIdx.x == 0) out[row] = sqrtf(sq);
}

__global__ __launch_bounds__(256)
void wvn_kernel(const float* __restrict__ probs, const float* __restrict__ tvn,
                float* __restrict__ out)
{
    long long i = (long long)blockIdx.x * blockDim.x + threadIdx.x;
    if (i >= (long long)BZ * TQ * SK) return;
    int s = (int)(i & 1023);
    long long bt = i >> 10;
    int t = (int)(bt & 1023);
    int b = (int)(bt >> 10);
    const float* p = probs + (long long)b * HH * TQ * SK + (long long)t * SK + s;
    float acc = 0.f;
#pragma unroll
    for (int h = 0; h < HH; h++) acc += p[(long long)h * TQ * SK];
    out[i] = acc * (1.0f / (float)HH) * tvn[b * SK + s];
}

// ---------------------------------------------------------------------------
// Host launcher
// ---------------------------------------------------------------------------
extern "C" void kernel_launch(void* const* d_in, const int* in_sizes, int n_in,
                              void* d_out, int out_size)
{
    const float* dec_in  = (const float*)d_in[0];
    const float* enc_out = (const float*)d_in[1];
    const unsigned char* en_mask = (const unsigned char*)d_in[2];
    const unsigned char* de_mask = (const unsigned char*)d_in[3];
    const float* ln_g   = (const float*)d_in[4];
    const float* ln_b   = (const float*)d_in[5];
    const float* w_in1  = (const float*)d_in[6];
    const float* b_in1  = (const float*)d_in[7];
    const float* w_out1 = (const float*)d_in[8];
    const float* b_out1 = (const float*)d_in[9];
    const float* w_in2  = (const float*)d_in[10];
    const float* b_in2  = (const float*)d_in[11];
    const float* w_out2 = (const float*)d_in[12];
    const float* b_out2 = (const float*)d_in[13];
    const float* mlp_w1 = (const float*)d_in[14];
    const float* mlp_b1 = (const float*)d_in[15];
    const float* mlp_w2 = (const float*)d_in[16];
    const float* mlp_b2 = (const float*)d_in[17];

    float *de_in, *qkv1, *scores, *ctx, *x, *enout, *q2, *kv2, *x2, *tv, *tvn, *lnx, *hbuf;
    cudaGetSymbolAddress((void**)&de_in,  g_de_in);
    cudaGetSymbolAddress((void**)&qkv1,   g_qkv1);
    cudaGetSymbolAddress((void**)&scores, g_scores);
    cudaGetSymbolAddress((void**)&ctx,    g_ctx);
    cudaGetSymbolAddress((void**)&x,      g_x);
    cudaGetSymbolAddress((void**)&enout,  g_enout);
    cudaGetSymbolAddress((void**)&q2,     g_q2);
    cudaGetSymbolAddress((void**)&kv2,    g_kv2);
    cudaGetSymbolAddress((void**)&x2,     g_x2);
    cudaGetSymbolAddress((void**)&tv,     g_tv);
    cudaGetSymbolAddress((void**)&tvn,    g_tvn);
    cudaGetSymbolAddress((void**)&lnx,    g_lnx);
    cudaGetSymbolAddress((void**)&hbuf,   g_h);

    float* out1 = (float*)d_out;
    float* out2 = (float*)d_out + (long long)BZ * TQ * DM;

    const int BT = BZ * TQ;
    const long long TSh = (long long)TQ * SK;
    const long long TSb = (long long)HH * TQ * SK;

    // smem bytes: stage halves = 2*(128*40) + 2*(BN*40); double-buffered, x2 bytes
    const int SM128 = 2 * (2 * 128 * 40 + 2 * 128 * 40) * 2; // 81920
    const int SM64  = 2 * (2 * 128 * 40 + 2 * 64 * 40) * 2;  // 61440
    cudaFuncSetAttribute(mma_gemm<128, true,  0>, cudaFuncAttributeMaxDynamicSharedMemorySize, SM128);
    cudaFuncSetAttribute(mma_gemm<128, true,  1>, cudaFuncAttributeMaxDynamicSharedMemorySize, SM128);
    cudaFuncSetAttribute(mma_gemm<128, false, 0>, cudaFuncAttributeMaxDynamicSharedMemorySize, SM128);
    cudaFuncSetAttribute(mma_gemm<64,  false, 0>, cudaFuncAttributeMaxDynamicSharedMemorySize, SM64);

    // 1-2: LayerNorms
    ln_kernel<<<BT, 256>>>(dec_in, de_in, ln_g, ln_b);
    ln_kernel<<<BT, 256>>>(enc_out, enout, ln_g, ln_b);

    // 3: QKV1 = de_in @ w_in1^T + b_in1
    mma_gemm<128, true, 0><<<dim3(3 * DM / 128, BT / 128, 1), 256, SM128>>>(
        de_in, DM, 0, 0,  w_in1, DM, 0, 0,  qkv1, 3 * DM, 0, 0,
        b_in1, nullptr, 0, DM, 1.0f, 1);

    // 4: self-attn scores = 0.125 * Q @ K^T
    mma_gemm<128, true, 0><<<dim3(SK / 128, TQ / 128, BZ * HH), 256, SM128>>>(
        qkv1,      3 * DM, (long long)TQ * 3 * DM, HD,
        qkv1 + DM, 3 * DM, (long long)SK * 3 * DM, HD,
        scores, SK, TSb, TSh,
        nullptr, nullptr, 0, HD, 0.125f, HH);

    // 5: causal softmax
    softmax_kernel<<<dim3(TQ, HH, BZ), 256>>>(scores, de_mask, 1);

    // 6: ctx = probs @ V
    mma_gemm<64, false, 0><<<dim3(1, TQ / 128, BZ * HH), 256, SM64>>>(
        scores, SK, TSb, TSh,
        qkv1 + 2 * DM, 3 * DM, (long long)SK * 3 * DM, HD,
        ctx, DM, (long long)TQ * DM, HD,
        nullptr, nullptr, 0, SK, 1.0f, HH);

    // 7: x = decoder_input + ctx @ w_out1^T + b_out1
    mma_gemm<128, true, 0><<<dim3(DM / 128, BT / 128, 1), 256, SM128>>>(
        ctx, DM, 0, 0,  w_out1, DM, 0, 0,  x, DM, 0, 0,
        b_out1, dec_in, DM, DM, 1.0f, 1);

    // 8: q2 = x @ wq2^T + bq2
    mma_gemm<128, true, 0><<<dim3(DM / 128, BT / 128, 1), 256, SM128>>>(
        x, DM, 0, 0,  w_in2, DM, 0, 0,  q2, DM, 0, 0,
        b_in2, nullptr, 0, DM, 1.0f, 1);

    // 9: kv2 = en_out @ w_kv2^T + b_kv2
    mma_gemm<128, true, 0><<<dim3(2 * DM / 128, BT / 128, 1), 256, SM128>>>(
        enout, DM, 0, 0,  w_in2 + (long long)DM * DM, DM, 0, 0,  kv2, 2 * DM, 0, 0,
        b_in2 + DM, nullptr, 0, DM, 1.0f, 1);

    // 10: cross-attn scores
    mma_gemm<128, true, 0><<<dim3(SK / 128, TQ / 128, BZ * HH), 256, SM128>>>(
        q2,  DM,     (long long)TQ * DM,     HD,
        kv2, 2 * DM, (long long)SK * 2 * DM, HD,
        scores, SK, TSb, TSh,
        nullptr, nullptr, 0, HD, 0.125f, HH);

    // 11: softmax (no causal)
    softmax_kernel<<<dim3(TQ, HH, BZ), 256>>>(scores, en_mask, 0);

    // 12: ctx = probs2 @ V2
    mma_gemm<64, false, 0><<<dim3(1, TQ / 128, BZ * HH), 256, SM64>>>(
        scores, SK, TSb, TSh,
        kv2 + DM, 2 * DM, (long long)SK * 2 * DM, HD,
        ctx, DM, (long long)TQ * DM, HD,
        nullptr, nullptr, 0, SK, 1.0f, HH);

    // 13: x2 = x + ctx @ w_out2^T + b_out2
    mma_gemm<128, true, 0><<<dim3(DM / 128, BT / 128, 1), 256, SM128>>>(
        ctx, DM, 0, 0,  w_out2, DM, 0, 0,  x2, DM, 0, 0,
        b_out2, x, DM, DM, 1.0f, 1);

    // 14: tv = en_out @ w_out2 (NOT transposed)
    mma_gemm<128, false, 0><<<dim3(DM / 128, BT / 128, 1), 256, SM128>>>(
        enout, DM, 0, 0,  w_out2, DM, 0, 0,  tv, DM, 0, 0,
        nullptr, nullptr, 0, DM, 1.0f, 1);

    // 15: tvnorm
    rownorm_kernel<<<BT, 256>>>(tv, tvn);

    // 16: wvn output
    {
        long long n = (long long)BZ * TQ * SK;
        wvn_kernel<<<(unsigned)((n + 255) / 256), 256>>>(scores, tvn, out2);
    }

    // 17: lnx = LN(x2)
    ln_kernel<<<BT, 256>>>(x2, lnx, ln_g, ln_b);

    // 18: h = gelu(lnx @ mlp_w1^T + mlp_b1)
    mma_gemm<128, true, 1><<<dim3(4 * DM / 128, BT / 128, 1), 256, SM128>>>(
        lnx, DM, 0, 0,  mlp_w1, DM, 0, 0,  hbuf, 4 * DM, 0, 0,
        mlp_b1, nullptr, 0, DM, 1.0f, 1);

    // 19: out1 = x2 + h @ mlp_w2^T + mlp_b2
    mma_gemm<128, true, 0><<<dim3(DM / 128, BT / 128, 1), 256, SM128>>>(
        hbuf, 4 * DM, 0, 0,  mlp_w2, 4 * DM, 0, 0,  out1, DM, 0, 0,
        mlp_b2, x2, DM, 4 * DM, 1.0f, 1);
}

// round 4
// speedup vs baseline: 2.5670x; 1.2566x over previous
#include <cuda_runtime.h>
#include <cuda_bf16.h>
#include <math.h>
#include <stdint.h>

#define BZ 4
#define TQ 1024
#define SK 1024
#define DM 1024
#define HH 16
#define HD 64

// ---------------------------------------------------------------------------
// Scratch
// ---------------------------------------------------------------------------
__device__ float g_de_in[BZ * TQ * DM];
__device__ float g_qkv1 [BZ * TQ * 3 * DM];
__device__ float g_scores[(long long)BZ * HH * TQ * SK];
__device__ float g_ctx  [BZ * TQ * DM];
__device__ float g_x    [BZ * TQ * DM];
__device__ float g_enout[BZ * SK * DM];
__device__ float g_q2   [BZ * TQ * DM];
__device__ float g_kv2  [BZ * SK * 2 * DM];
__device__ float g_x2   [BZ * TQ * DM];
__device__ float g_tv   [BZ * SK * DM];
__device__ float g_tvn  [BZ * SK];
__device__ float g_lnx  [BZ * TQ * DM];
__device__ float g_h    [BZ * TQ * 4 * DM];

// ---------------------------------------------------------------------------
// MMA / ldmatrix primitives
// ---------------------------------------------------------------------------
__device__ __forceinline__ uint32_t smem_u32(const void* p) {
    uint32_t a;
    asm("{ .reg .u64 t; cvta.to.shared.u64 t, %1; cvt.u32.u64 %0, t; }" : "=r"(a) : "l"(p));
    return a;
}
__device__ __forceinline__ void ldsm_x4(uint32_t addr, uint32_t* r) {
    asm volatile("ldmatrix.sync.aligned.m8n8.x4.shared.b16 {%0,%1,%2,%3}, [%4];"
        : "=r"(r[0]), "=r"(r[1]), "=r"(r[2]), "=r"(r[3]) : "r"(addr));
}
__device__ __forceinline__ void ldsm_x4_t(uint32_t addr, uint32_t* r) {
    asm volatile("ldmatrix.sync.aligned.m8n8.x4.trans.shared.b16 {%0,%1,%2,%3}, [%4];"
        : "=r"(r[0]), "=r"(r[1]), "=r"(r[2]), "=r"(r[3]) : "r"(addr));
}
__device__ __forceinline__ void mma_bf16(float* c, const uint32_t* a, const uint32_t* b) {
    asm volatile("mma.sync.aligned.m16n8k16.row.col.f32.bf16.bf16.f32 "
        "{%0,%1,%2,%3}, {%4,%5,%6,%7}, {%8,%9}, {%0,%1,%2,%3};"
        : "+f"(c[0]), "+f"(c[1]), "+f"(c[2]), "+f"(c[3])
        : "r"(a[0]), "r"(a[1]), "r"(a[2]), "r"(a[3]), "r"(b[0]), "r"(b[1]));
}
__device__ __forceinline__ void split_bf16(float f, unsigned short& h, unsigned short& l) {
    __nv_bfloat16 bh = __float2bfloat16(f);
    float fl = f - __bfloat162float(bh);
    __nv_bfloat16 bl = __float2bfloat16(fl);
    h = __bfloat16_as_ushort(bh);
    l = __bfloat16_as_ushort(bl);
}
__device__ __forceinline__ uint32_t packhi2(float a, float b) {
    __nv_bfloat162 t = __floats2bfloat162_rn(a, b);
    return *reinterpret_cast<uint32_t*>(&t);
}
__device__ __forceinline__ uint32_t packlo2(float a, float b) {
    float la = a - __bfloat162float(__float2bfloat16(a));
    float lb = b - __bfloat162float(__float2bfloat16(b));
    return packhi2(la, lb);
}

// ---------------------------------------------------------------------------
// GEMM v2: 512 threads, 16 warps (4m x 4n), CTA tile 128 x BN, BK=32.
// bf16 3-term split. Double buffer, register prefetch, one sync/iter.
// ---------------------------------------------------------------------------
template<int BN, bool TRANSB, int ACT>
__global__ __launch_bounds__(512, 1)
void gemm512(const float* __restrict__ A, int lda, long long Ab, long long Ah,
             const float* __restrict__ B, int ldb, long long Bb, long long Bh,
             float* __restrict__ C, int ldc, long long Cb, long long Ch,
             const float* __restrict__ bias,
             const float* __restrict__ res, int ldr,
             int K, float alpha, int nh)
{
    constexpr int PITCH = 40;            // halves (80 B rows, ldsm conflict-free)
    constexpr int ASZ = 128 * PITCH;
    constexpr int BSZ = BN * PITCH;
    constexpr int STAGE = 2 * ASZ + 2 * BSZ;
    constexpr int WN = BN / 4;           // warp tile n (32 or 16)
    constexpr int NT = WN / 8;           // n8 tiles per warp (4 or 2)
    constexpr int NB4 = BN / 64;         // B float4 loads per thread (2 or 1)
    constexpr int NC4 = BN / 4;

    extern __shared__ __align__(128) unsigned short sm[];

    const int tid = threadIdx.x;
    const int lane = tid & 31;
    const int wid = tid >> 5;
    const int wm = (wid & 3) * 32;
    const int wn = (wid >> 2) * WN;

    const int bz = blockIdx.z;
    const int bb = bz / nh;
    const int hh = bz - bb * nh;
    const int m0 = blockIdx.y * 128;
    const int n0 = blockIdx.x * BN;

    const float* Ag = A + bb * Ab + hh * Ah + (long long)m0 * lda;
    const float* Bg = B + bb * Bb + hh * Bh + (TRANSB ? (long long)n0 * ldb : (long long)n0);
    float* Cg = C + bb * Cb + hh * Ch;

    float acc[2][NT][4];
#pragma unroll
    for (int mi = 0; mi < 2; mi++)
#pragma unroll
        for (int ni = 0; ni < NT; ni++)
#pragma unroll
            for (int j = 0; j < 4; j++) acc[mi][ni][j] = 0.0f;

    const uint32_t sb0 = smem_u32(sm);
    const int nk = K >> 5;

    float4 sa[2], sbv[NB4];

    auto loadA = [&](int k0) {
#pragma unroll
        for (int u = 0; u < 2; u++) {
            int idx = tid + u * 512;
            int row = idx >> 3, c4 = idx & 7;
            sa[u] = *(const float4*)(Ag + (long long)row * lda + k0 + c4 * 4);
        }
    };
    auto loadB = [&](int k0) {
        if (TRANSB) {
#pragma unroll
            for (int u = 0; u < NB4; u++) {
                int idx = tid + u * 512;
                int row = idx >> 3, c4 = idx & 7;
                sbv[u] = *(const float4*)(Bg + (long long)row * ldb + k0 + c4 * 4);
            }
        } else {
#pragma unroll
            for (int u = 0; u < NB4; u++) {
                int idx = tid + u * 512;
                int kr = idx / NC4, nc4 = idx - kr * NC4;
                sbv[u] = *(const float4*)(Bg + (long long)(k0 + kr) * ldb + nc4 * 4);
            }
        }
    };
    auto storeStage = [&](int buf) {
        unsigned short* sAhi = sm + buf * STAGE;
        unsigned short* sAlo = sAhi + ASZ;
        unsigned short* sBhi = sAlo + ASZ;
        unsigned short* sBlo = sBhi + BSZ;
#pragma unroll
        for (int u = 0; u < 2; u++) {
            int idx = tid + u * 512;
            int row = idx >> 3, c4 = idx & 7;
            float4 v = sa[u];
            unsigned short h0,h1,h2,h3,l0,l1,l2,l3;
            split_bf16(v.x,h0,l0); split_bf16(v.y,h1,l1);
            split_bf16(v.z,h2,l2); split_bf16(v.w,h3,l3);
            int off = row * PITCH + c4 * 4;
            *(uint2*)(sAhi + off) = make_uint2((uint32_t)h0 | ((uint32_t)h1 << 16),
                                               (uint32_t)h2 | ((uint32_t)h3 << 16));
            *(uint2*)(sAlo + off) = make_uint2((uint32_t)l0 | ((uint32_t)l1 << 16),
                                               (uint32_t)l2 | ((uint32_t)l3 << 16));
        }
        if (TRANSB) {
#pragma unroll
            for (int u = 0; u < NB4; u++) {
                int idx = tid + u * 512;
                int row = idx >> 3, c4 = idx & 7;
                float4 v = sbv[u];
                unsigned short h0,h1,h2,h3,l0,l1,l2,l3;
                split_bf16(v.x,h0,l0); split_bf16(v.y,h1,l1);
                split_bf16(v.z,h2,l2); split_bf16(v.w,h3,l3);
                int off = row * PITCH + c4 * 4;
                *(uint2*)(sBhi + off) = make_uint2((uint32_t)h0 | ((uint32_t)h1 << 16),
                                                   (uint32_t)h2 | ((uint32_t)h3 << 16));
                *(uint2*)(sBlo + off) = make_uint2((uint32_t)l0 | ((uint32_t)l1 << 16),
                                                   (uint32_t)l2 | ((uint32_t)l3 << 16));
            }
        } else {
#pragma unroll
            for (int u = 0; u < NB4; u++) {
                int idx = tid + u * 512;
                int kr = idx / NC4, nc4 = idx - kr * NC4;
                float4 v = sbv[u];
                float f[4] = {v.x, v.y, v.z, v.w};
#pragma unroll
                for (int j = 0; j < 4; j++) {
                    unsigned short h, l;
                    split_bf16(f[j], h, l);
                    int off = (nc4 * 4 + j) * PITCH + kr;
                    sBhi[off] = h;
                    sBlo[off] = l;
                }
            }
        }
    };

    // prologue
    loadA(0); loadB(0);
    storeStage(0);
    __syncthreads();

    for (int k = 0; k < nk; k++) {
        const int buf = k & 1;
        if (k + 1 < nk) { loadA((k + 1) << 5); loadB((k + 1) << 5); }

        uint32_t base = sb0 + (uint32_t)buf * STAGE * 2;
#pragma unroll
        for (int kk = 0; kk < 32; kk += 16) {
            uint32_t ah[2][4], al_[2][4];
            int arow = wm + (lane & 15);
            int acol = kk + ((lane >> 4) << 3);
#pragma unroll
            for (int mi = 0; mi < 2; mi++) {
                uint32_t ad = base + (uint32_t)((((arow + mi * 16) * PITCH) + acol) * 2);
                ldsm_x4(ad, ah[mi]);
                ldsm_x4(ad + ASZ * 2, al_[mi]);
            }
            uint32_t bh_[NT][2], bl_[NT][2];
            int brow = wn + (lane & 7) + ((lane & 16) >> 1);
            int bcol = kk + (((lane >> 3) & 1) << 3);
#pragma unroll
            for (int nj = 0; nj < NT / 2; nj++) {
                uint32_t bd = base + (uint32_t)((2 * ASZ + (brow + nj * 16) * PITCH + bcol) * 2);
                uint32_t r[4];
                ldsm_x4(bd, r);
                bh_[2 * nj][0] = r[0]; bh_[2 * nj][1] = r[1];
                bh_[2 * nj + 1][0] = r[2]; bh_[2 * nj + 1][1] = r[3];
                ldsm_x4(bd + BSZ * 2, r);
                bl_[2 * nj][0] = r[0]; bl_[2 * nj][1] = r[1];
                bl_[2 * nj + 1][0] = r[2]; bl_[2 * nj + 1][1] = r[3];
            }
#pragma unroll
            for (int mi = 0; mi < 2; mi++)
#pragma unroll
                for (int ni = 0; ni < NT; ni++) {
                    mma_bf16(acc[mi][ni], ah[mi], bh_[ni]);
                    mma_bf16(acc[mi][ni], ah[mi], bl_[ni]);
                    mma_bf16(acc[mi][ni], al_[mi], bh_[ni]);
                }
        }
        if (k + 1 < nk) storeStage(buf ^ 1);
        __syncthreads();
    }

    // epilogue
#pragma unroll
    for (int mi = 0; mi < 2; mi++) {
#pragma unroll
        for (int ni = 0; ni < NT; ni++) {
            int m = m0 + wm + mi * 16 + (lane >> 2);
            int n = n0 + wn + ni * 8 + (lane & 3) * 2;
#pragma unroll
            for (int rr = 0; rr < 2; rr++) {
                int mm = m + rr * 8;
                float v0 = acc[mi][ni][rr * 2 + 0] * alpha;
                float v1 = acc[mi][ni][rr * 2 + 1] * alpha;
                if (bias) { v0 += bias[n]; v1 += bias[n + 1]; }
                if (ACT == 1) {
                    v0 = 0.5f * v0 * (1.0f + erff(v0 * 0.70710678118654752f));
                    v1 = 0.5f * v1 * (1.0f + erff(v1 * 0.70710678118654752f));
                }
                if (res) {
                    v0 += res[(long long)mm * ldr + n];
                    v1 += res[(long long)mm * ldr + n + 1];
                }
                *(float2*)(Cg + (long long)mm * ldc + n) = make_float2(v0, v1);
            }
        }
    }
}

// ---------------------------------------------------------------------------
// Flash self-attention (causal + key-padding). 128 threads, 4 warps.
// CTA: 64 q-rows for one (b,h). Chunks of 64 keys. 3-term bf16 split both MMAs.
// ctx[b, t, h*64+d] output (fp32).
// ---------------------------------------------------------------------------
__global__ __launch_bounds__(128)
void flash_self(const float* __restrict__ qkv, const unsigned char* __restrict__ kpm,
                float* __restrict__ ctx)
{
    constexpr int P = 72;                 // halves per row
    constexpr int TSZ = 64 * P;           // 4608 halves per component
    extern __shared__ __align__(128) unsigned short fs[];
    unsigned short* sQh = fs;
    unsigned short* sQl = sQh + TSZ;
    unsigned short* sKh = sQl + TSZ;
    unsigned short* sKl = sKh + TSZ;
    unsigned short* sVh = sKl + TSZ;
    unsigned short* sVl = sVh + TSZ;
    unsigned char* smask = (unsigned char*)(sVl + TSZ);

    const int tid = threadIdx.x, lane = tid & 31, wid = tid >> 5;
    const int bx = blockIdx.x;
    const int bh = blockIdx.y;
    const int b = bh >> 4, h = bh & 15;
    const int t0 = bx * 64;

    const float* Qg = qkv + ((long long)b * TQ + t0) * 3 * DM + h * HD;
    const float* Kg = qkv + ((long long)b * TQ) * 3 * DM + DM + h * HD;
    const float* Vg = qkv + ((long long)b * TQ) * 3 * DM + 2 * DM + h * HD;
    const unsigned char* kp = kpm + (long long)b * SK;

    // load Q tile (64 x 64), split hi/lo
#pragma unroll
    for (int u = 0; u < 8; u++) {
        int idx = tid + u * 128;
        int r = idx >> 4, c4 = idx & 15;
        float4 v = *(const float4*)(Qg + (long long)r * 3 * DM + c4 * 4);
        unsigned short h0,h1,h2,h3,l0,l1,l2,l3;
        split_bf16(v.x,h0,l0); split_bf16(v.y,h1,l1);
        split_bf16(v.z,h2,l2); split_bf16(v.w,h3,l3);
        int off = r * P + c4 * 4;
        *(uint2*)(sQh + off) = make_uint2((uint32_t)h0 | ((uint32_t)h1 << 16),
                                          (uint32_t)h2 | ((uint32_t)h3 << 16));
        *(uint2*)(sQl + off) = make_uint2((uint32_t)l0 | ((uint32_t)l1 << 16),
                                          (uint32_t)l2 | ((uint32_t)l3 << 16));
    }

    float o[8][4];
#pragma unroll
    for (int i = 0; i < 8; i++)
#pragma unroll
        for (int j = 0; j < 4; j++) o[i][j] = 0.0f;
    float mrow0 = -1e30f, mrow1 = -1e30f, lrow0 = 0.0f, lrow1 = 0.0f;

    const uint32_t qb = smem_u32(sQh);
    const uint32_t kb = smem_u32(sKh);
    const uint32_t vb = smem_u32(sVh);

    const int nch = bx + 1;
    for (int ch = 0; ch < nch; ch++) {
        const int s0 = ch * 64;
        __syncthreads();   // protect K/V/mask from previous iteration's readers
        // load K, V chunks
#pragma unroll
        for (int u = 0; u < 8; u++) {
            int idx = tid + u * 128;
            int r = idx >> 4, c4 = idx & 15;
            float4 v = *(const float4*)(Kg + (long long)(s0 + r) * 3 * DM + c4 * 4);
            unsigned short h0,h1,h2,h3,l0,l1,l2,l3;
            split_bf16(v.x,h0,l0); split_bf16(v.y,h1,l1);
            split_bf16(v.z,h2,l2); split_bf16(v.w,h3,l3);
            int off = r * P + c4 * 4;
            *(uint2*)(sKh + off) = make_uint2((uint32_t)h0 | ((uint32_t)h1 << 16),
                                              (uint32_t)h2 | ((uint32_t)h3 << 16));
            *(uint2*)(sKl + off) = make_uint2((uint32_t)l0 | ((uint32_t)l1 << 16),
                                              (uint32_t)l2 | ((uint32_t)l3 << 16));
            v = *(const float4*)(Vg + (long long)(s0 + r) * 3 * DM + c4 * 4);
            split_bf16(v.x,h0,l0); split_bf16(v.y,h1,l1);
            split_bf16(v.z,h2,l2); split_bf16(v.w,h3,l3);
            *(uint2*)(sVh + off) = make_uint2((uint32_t)h0 | ((uint32_t)h1 << 16),
                                              (uint32_t)h2 | ((uint32_t)h3 << 16));
            *(uint2*)(sVl + off) = make_uint2((uint32_t)l0 | ((uint32_t)l1 << 16),
                                              (uint32_t)l2 | ((uint32_t)l3 << 16));
        }
        if (tid < 64) smask[tid] = kp[s0 + tid];
        __syncthreads();

        // ---- S = 0.125 * Q K^T ----
        float sc[8][4];
#pragma unroll
        for (int i = 0; i < 8; i++)
#pragma unroll
            for (int j = 0; j < 4; j++) sc[i][j] = 0.0f;

#pragma unroll
        for (int kt = 0; kt < 4; kt++) {
            uint32_t aq[4], al_[4];
            uint32_t ad = qb + (uint32_t)(((wid * 16 + (lane & 15)) * P + kt * 16 + ((lane >> 4) << 3)) * 2);
            ldsm_x4(ad, aq);
            ldsm_x4(ad + TSZ * 2, al_);
            uint32_t bh_[8][2], bl_[8][2];
#pragma unroll
            for (int nj = 0; nj < 4; nj++) {
                uint32_t bd = kb + (uint32_t)(((nj * 16 + (lane & 7) + ((lane & 16) >> 1)) * P
                                              + kt * 16 + (((lane >> 3) & 1) << 3)) * 2);
                uint32_t r[4];
                ldsm_x4(bd, r);
                bh_[2*nj][0]=r[0]; bh_[2*nj][1]=r[1]; bh_[2*nj+1][0]=r[2]; bh_[2*nj+1][1]=r[3];
                ldsm_x4(bd + TSZ * 2, r);
                bl_[2*nj][0]=r[0]; bl_[2*nj][1]=r[1]; bl_[2*nj+1][0]=r[2]; bl_[2*nj+1][1]=r[3];
            }
#pragma unroll
            for (int ni = 0; ni < 8; ni++) {
                mma_bf16(sc[ni], aq, bh_[ni]);
                mma_bf16(sc[ni], aq, bl_[ni]);
                mma_bf16(sc[ni], al_, bh_[ni]);
            }
        }

        // ---- mask + scale ----
        const int gr0 = t0 + wid * 16 + (lane >> 2);
#pragma unroll
        for (int ni = 0; ni < 8; ni++) {
#pragma unroll
            for (int j = 0; j < 4; j++) {
                int rr = gr0 + ((j >> 1) << 3);
                int cl = ni * 8 + (lane & 3) * 2 + (j & 1);
                float xv = sc[ni][j] * 0.125f;
                if (s0 + cl > rr) xv -= 1e9f;
                if (smask[cl]) xv = -1e9f;
                sc[ni][j] = xv;
            }
        }

        // ---- online softmax ----
        float mc0 = -1e30f, mc1 = -1e30f;
#pragma unroll
        for (int ni = 0; ni < 8; ni++) {
            mc0 = fmaxf(mc0, fmaxf(sc[ni][0], sc[ni][1]));
            mc1 = fmaxf(mc1, fmaxf(sc[ni][2], sc[ni][3]));
        }
#pragma unroll
        for (int off = 1; off <= 2; off <<= 1) {
            mc0 = fmaxf(mc0, __shfl_xor_sync(0xffffffffu, mc0, off));
            mc1 = fmaxf(mc1, __shfl_xor_sync(0xffffffffu, mc1, off));
        }
        float mn0 = fmaxf(mrow0, mc0), mn1 = fmaxf(mrow1, mc1);
        float scale0 = __expf(mrow0 - mn0), scale1 = __expf(mrow1 - mn1);
        float ls0 = 0.0f, ls1 = 0.0f;
#pragma unroll
        for (int ni = 0; ni < 8; ni++) {
            sc[ni][0] = __expf(sc[ni][0] - mn0);
            sc[ni][1] = __expf(sc[ni][1] - mn0);
            sc[ni][2] = __expf(sc[ni][2] - mn1);
            sc[ni][3] = __expf(sc[ni][3] - mn1);
            ls0 += sc[ni][0] + sc[ni][1];
            ls1 += sc[ni][2] + sc[ni][3];
        }
#pragma unroll
        for (int off = 1; off <= 2; off <<= 1) {
            ls0 += __shfl_xor_sync(0xffffffffu, ls0, off);
            ls1 += __shfl_xor_sync(0xffffffffu, ls1, off);
        }
        lrow0 = lrow0 * scale0 + ls0;
        lrow1 = lrow1 * scale1 + ls1;
        mrow0 = mn0; mrow1 = mn1;
#pragma unroll
        for (int ni = 0; ni < 8; ni++) {
            o[ni][0] *= scale0; o[ni][1] *= scale0;
            o[ni][2] *= scale1; o[ni][3] *= scale1;
        }

        // ---- O += P @ V ----
#pragma unroll
        for (int kt = 0; kt < 4; kt++) {
            uint32_t ph[4], pl[4];
            ph[0] = packhi2(sc[2*kt][0],   sc[2*kt][1]);
            ph[1] = packhi2(sc[2*kt][2],   sc[2*kt][3]);
            ph[2] = packhi2(sc[2*kt+1][0], sc[2*kt+1][1]);
            ph[3] = packhi2(sc[2*kt+1][2], sc[2*kt+1][3]);
            pl[0] = packlo2(sc[2*kt][0],   sc[2*kt][1]);
            pl[1] = packlo2(sc[2*kt][2],   sc[2*kt][3]);
            pl[2] = packlo2(sc[2*kt+1][0], sc[2*kt+1][1]);
            pl[3] = packlo2(sc[2*kt+1][2], sc[2*kt+1][3]);

            uint32_t vh_[8][2], vl_[8][2];
#pragma unroll
            for (int nj = 0; nj < 4; nj++) {
                uint32_t bd = vb + (uint32_t)(((kt * 16 + (lane & 15)) * P
                                              + nj * 16 + ((lane >> 4) << 3)) * 2);
                uint32_t r[4];
                ldsm_x4_t(bd, r);
                vh_[2*nj][0]=r[0]; vh_[2*nj][1]=r[1]; vh_[2*nj+1][0]=r[2]; vh_[2*nj+1][1]=r[3];
                ldsm_x4_t(bd + TSZ * 2, r);
                vl_[2*nj][0]=r[0]; vl_[2*nj][1]=r[1]; vl_[2*nj+1][0]=r[2]; vl_[2*nj+1][1]=r[3];
            }
#pragma unroll
            for (int ni = 0; ni < 8; ni++) {
                mma_bf16(o[ni], ph, vh_[ni]);
                mma_bf16(o[ni], ph, vl_[ni]);
                mma_bf16(o[ni], pl, vh_[ni]);
            }
        }
    }

    // ---- write ctx ----
    float inv0 = 1.0f / fmaxf(lrow0, 1e-30f);
    float inv1 = 1.0f / fmaxf(lrow1, 1e-30f);
    float* Cg = ctx + ((long long)b * TQ) * DM + h * HD;
    const int r0 = t0 + wid * 16 + (lane >> 2);
#pragma unroll
    for (int ni = 0; ni < 8; ni++) {
        int c = ni * 8 + (lane & 3) * 2;
        *(float2*)(Cg + (long long)r0 * DM + c)       = make_float2(o[ni][0] * inv0, o[ni][1] * inv0);
        *(float2*)(Cg + (long long)(r0 + 8) * DM + c) = make_float2(o[ni][2] * inv1, o[ni][3] * inv1);
    }
}

// ---------------------------------------------------------------------------
// Reductions / LN / softmax / rownorm / wvn
// ---------------------------------------------------------------------------
__device__ __forceinline__ float block_sum(float v, float* sh) {
#pragma unroll
    for (int o = 16; o > 0; o >>= 1) v += __shfl_xor_sync(0xffffffffu, v, o);
    if ((threadIdx.x & 31) == 0) sh[threadIdx.x >> 5] = v;
    __syncthreads();
    if (threadIdx.x < 32) {
        float w = (threadIdx.x < 8) ? sh[threadIdx.x] : 0.0f;
#pragma unroll
        for (int o = 4; o > 0; o >>= 1) w += __shfl_xor_sync(0xffffffffu, w, o);
        if (threadIdx.x == 0) sh[0] = w;
    }
    __syncthreads();
    float r = sh[0];
    __syncthreads();
    return r;
}
__device__ __forceinline__ float block_max(float v, float* sh) {
#pragma unroll
    for (int o = 16; o > 0; o >>= 1) v = fmaxf(v, __shfl_xor_sync(0xffffffffu, v, o));
    if ((threadIdx.x & 31) == 0) sh[threadIdx.x >> 5] = v;
    __syncthreads();
    if (threadIdx.x < 32) {
        float w = (threadIdx.x < 8) ? sh[threadIdx.x] : -3.4e38f;
#pragma unroll
        for (int o = 4; o > 0; o >>= 1) w = fmaxf(w, __shfl_xor_sync(0xffffffffu, w, o));
        if (threadIdx.x == 0) sh[0] = w;
    }
    __syncthreads();
    float r = sh[0];
    __syncthreads();
    return r;
}

__global__ __launch_bounds__(256)
void ln_kernel(const float* __restrict__ x, float* __restrict__ y,
               const float* __restrict__ g, const float* __restrict__ beta)
{
    __shared__ float sh[32];
    const long long row = blockIdx.x;
    const float* xr = x + row * DM;
    float* yr = y + row * DM;
    const int tid = threadIdx.x;
    float v[4];
    float s = 0.f, sq = 0.f;
#pragma unroll
    for (int i = 0; i < 4; i++) {
        float t = xr[tid + 256 * i];
        v[i] = t; s += t; sq += t * t;
    }
    s  = block_sum(s, sh);
    sq = block_sum(sq, sh);
    float mean = s * (1.0f / 1024.0f);
    float var  = fmaxf(sq * (1.0f / 1024.0f) - mean * mean, 0.0f);
    float inv  = rsqrtf(var + 1e-6f);
#pragma unroll
    for (int i = 0; i < 4; i++) {
        int c = tid + 256 * i;
        yr[c] = (v[i] - mean) * inv * g[c] + beta[c];
    }
}

__global__ __launch_bounds__(256)
void softmax_kernel(float* __restrict__ sc, const unsigned char* __restrict__ kpm,
                    int causal)
{
    __shared__ float sh[32];
    const int t = blockIdx.x, h = blockIdx.y, b = blockIdx.z;
    float* row = sc + (((long long)(b * HH + h)) * TQ + t) * SK;
    const unsigned char* kp = kpm + (long long)b * SK;
    const int tid = threadIdx.x;
    float v[4];
    float mx = -3.4e38f;
#pragma unroll
    for (int i = 0; i < 4; i++) {
        int s = tid + 256 * i;
        float x = row[s];
        if (causal && s > t) x -= 1e9f;
        if (kp[s]) x = -1e9f;
        v[i] = x;
        mx = fmaxf(mx, x);
    }
    mx = block_max(mx, sh);
    float sum = 0.f;
#pragma unroll
    for (int i = 0; i < 4; i++) {
        v[i] = __expf(v[i] - mx);
        sum += v[i];
    }
    sum = block_sum(sum, sh);
    float inv = 1.0f / sum;
#pragma unroll
    for (int i = 0; i < 4; i++) row[tid + 256 * i] = v[i] * inv;
}

__global__ __launch_bounds__(256)
void rownorm_kernel(const float* __restrict__ x, float* __restrict__ out)
{
    __shared__ float sh[32];
    const long long row = blockIdx.x;
    const float* xr = x + row * DM;
    float sq = 0.f;
#pragma unroll
    for (int i = 0; i < 4; i++) {
        float t = xr[threadIdx.x + 256 * i];
        sq += t * t;
    }
    sq = block_sum(sq, sh);
    if (threadIdx.x == 0) out[row] = sqrtf(sq);
}

__global__ __launch_bounds__(256)
void wvn_kernel(const float* __restrict__ probs, const float* __restrict__ tvn,
                float* __restrict__ out)
{
    long long i = (long long)blockIdx.x * blockDim.x + threadIdx.x;
    if (i >= (long long)BZ * TQ * SK) return;
    int s = (int)(i & 1023);
    long long bt = i >> 10;
    int t = (int)(bt & 1023);
    int b = (int)(bt >> 10);
    const float* p = probs + (long long)b * HH * TQ * SK + (long long)t * SK + s;
    float acc = 0.f;
#pragma unroll
    for (int h = 0; h < HH; h++) acc += p[(long long)h * TQ * SK];
    out[i] = acc * (1.0f / (float)HH) * tvn[b * SK + s];
}

// ---------------------------------------------------------------------------
// Host launcher
// ---------------------------------------------------------------------------
extern "C" void kernel_launch(void* const* d_in, const int* in_sizes, int n_in,
                              void* d_out, int out_size)
{
    const float* dec_in  = (const float*)d_in[0];
    const float* enc_out = (const float*)d_in[1];
    const unsigned char* en_mask = (const unsigned char*)d_in[2];
    const unsigned char* de_mask = (const unsigned char*)d_in[3];
    const float* ln_g   = (const float*)d_in[4];
    const float* ln_b   = (const float*)d_in[5];
    const float* w_in1  = (const float*)d_in[6];
    const float* b_in1  = (const float*)d_in[7];
    const float* w_out1 = (const float*)d_in[8];
    const float* b_out1 = (const float*)d_in[9];
    const float* w_in2  = (const float*)d_in[10];
    const float* b_in2  = (const float*)d_in[11];
    const float* w_out2 = (const float*)d_in[12];
    const float* b_out2 = (const float*)d_in[13];
    const float* mlp_w1 = (const float*)d_in[14];
    const float* mlp_b1 = (const float*)d_in[15];
    const float* mlp_w2 = (const float*)d_in[16];
    const float* mlp_b2 = (const float*)d_in[17];

    float *de_in, *qkv1, *scores, *ctx, *x, *enout, *q2, *kv2, *x2, *tv, *tvn, *lnx, *hbuf;
    cudaGetSymbolAddress((void**)&de_in,  g_de_in);
    cudaGetSymbolAddress((void**)&qkv1,   g_qkv1);
    cudaGetSymbolAddress((void**)&scores, g_scores);
    cudaGetSymbolAddress((void**)&ctx,    g_ctx);
    cudaGetSymbolAddress((void**)&x,      g_x);
    cudaGetSymbolAddress((void**)&enout,  g_enout);
    cudaGetSymbolAddress((void**)&q2,     g_q2);
    cudaGetSymbolAddress((void**)&kv2,    g_kv2);
    cudaGetSymbolAddress((void**)&x2,     g_x2);
    cudaGetSymbolAddress((void**)&tv,     g_tv);
    cudaGetSymbolAddress((void**)&tvn,    g_tvn);
    cudaGetSymbolAddress((void**)&lnx,    g_lnx);
    cudaGetSymbolAddress((void**)&hbuf,   g_h);

    float* out1 = (float*)d_out;
    float* out2 = (float*)d_out + (long long)BZ * TQ * DM;

    const int BT = BZ * TQ;
    const long long TSh = (long long)TQ * SK;
    const long long TSb = (long long)HH * TQ * SK;

    const int SM128 = 2 * (2 * 128 * 40 + 2 * 128 * 40) * 2; // 81920
    const int SM64  = 2 * (2 * 128 * 40 + 2 * 64 * 40) * 2;  // 61440
    const int SMFL  = 6 * 64 * 72 * 2 + 128;                  // 55424
    cudaFuncSetAttribute(gemm512<128, true,  0>, cudaFuncAttributeMaxDynamicSharedMemorySize, SM128);
    cudaFuncSetAttribute(gemm512<128, true,  1>, cudaFuncAttributeMaxDynamicSharedMemorySize, SM128);
    cudaFuncSetAttribute(gemm512<128, false, 0>, cudaFuncAttributeMaxDynamicSharedMemorySize, SM128);
    cudaFuncSetAttribute(gemm512<64,  false, 0>, cudaFuncAttributeMaxDynamicSharedMemorySize, SM64);
    cudaFuncSetAttribute(flash_self, cudaFuncAttributeMaxDynamicSharedMemorySize, SMFL);

    // 1-2: LayerNorms
    ln_kernel<<<BT, 256>>>(dec_in, de_in, ln_g, ln_b);
    ln_kernel<<<BT, 256>>>(enc_out, enout, ln_g, ln_b);

    // 3: QKV1 = de_in @ w_in1^T + b_in1
    gemm512<128, true, 0><<<dim3(3 * DM / 128, BT / 128, 1), 512, SM128>>>(
        de_in, DM, 0, 0,  w_in1, DM, 0, 0,  qkv1, 3 * DM, 0, 0,
        b_in1, nullptr, 0, DM, 1.0f, 1);

    // 4-6: fused flash self-attention (causal) -> ctx
    flash_self<<<dim3(TQ / 64, BZ * HH), 128, SMFL>>>(qkv1, de_mask, ctx);

    // 7: x = decoder_input + ctx @ w_out1^T + b_out1
    gemm512<128, true, 0><<<dim3(DM / 128, BT / 128, 1), 512, SM128>>>(
        ctx, DM, 0, 0,  w_out1, DM, 0, 0,  x, DM, 0, 0,
        b_out1, dec_in, DM, DM, 1.0f, 1);

    // 8: q2 = x @ wq2^T + bq2
    gemm512<128, true, 0><<<dim3(DM / 128, BT / 128, 1), 512, SM128>>>(
        x, DM, 0, 0,  w_in2, DM, 0, 0,  q2, DM, 0, 0,
        b_in2, nullptr, 0, DM, 1.0f, 1);

    // 9: kv2 = en_out @ w_kv2^T + b_kv2
    gemm512<128, true, 0><<<dim3(2 * DM / 128, BT / 128, 1), 512, SM128>>>(
        enout, DM, 0, 0,  w_in2 + (long long)DM * DM, DM, 0, 0,  kv2, 2 * DM, 0, 0,
        b_in2 + DM, nullptr, 0, DM, 1.0f, 1);

    // 10: cross-attn scores
    gemm512<128, true, 0><<<dim3(SK / 128, TQ / 128, BZ * HH), 512, SM128>>>(
        q2,  DM,     (long long)TQ * DM,     HD,
        kv2, 2 * DM, (long long)SK * 2 * DM, HD,
        scores, SK, TSb, TSh,
        nullptr, nullptr, 0, HD, 0.125f, HH);

    // 11: softmax (no causal)
    softmax_kernel<<<dim3(TQ, HH, BZ), 256>>>(scores, en_mask, 0);

    // 12: ctx = probs2 @ V2
    gemm512<64, false, 0><<<dim3(1, TQ / 128, BZ * HH), 512, SM64>>>(
        scores, SK, TSb, TSh,
        kv2 + DM, 2 * DM, (long long)SK * 2 * DM, HD,
        ctx, DM, (long long)TQ * DM, HD,
        nullptr, nullptr, 0, SK, 1.0f, HH);

    // 13: x2 = x + ctx @ w_out2^T + b_out2
    gemm512<128, true, 0><<<dim3(DM / 128, BT / 128, 1), 512, SM128>>>(
        ctx, DM, 0, 0,  w_out2, DM, 0, 0,  x2, DM, 0, 0,
        b_out2, x, DM, DM, 1.0f, 1);

    // 14: tv = en_out @ w_out2 (NOT transposed)
    gemm512<128, false, 0><<<dim3(DM / 128, BT / 128, 1), 512, SM128>>>(
        enout, DM, 0, 0,  w_out2, DM, 0, 0,  tv, DM, 0, 0,
        nullptr, nullptr, 0, DM, 1.0f, 1);

    // 15: tvnorm
    rownorm_kernel<<<BT, 256>>>(tv, tvn);

    // 16: wvn output
    {
        long long n = (long long)BZ * TQ * SK;
        wvn_kernel<<<(unsigned)((n + 255) / 256), 256>>>(scores, tvn, out2);
    }

    // 17: lnx = LN(x2)
    ln_kernel<<<BT, 256>>>(x2, lnx, ln_g, ln_b);

    // 18: h = gelu(lnx @ mlp_w1^T + mlp_b1)
    gemm512<128, true, 1><<<dim3(4 * DM / 128, BT / 128, 1), 512, SM128>>>(
        lnx, DM, 0, 0,  mlp_w1, DM, 0, 0,  hbuf, 4 * DM, 0, 0,
        mlp_b1, nullptr, 0, DM, 1.0f, 1);

    // 19: out1 = x2 + h @ mlp_w2^T + mlp_b2
    gemm512<128, true, 0><<<dim3(DM / 128, BT / 128, 1), 512, SM128>>>(
        hbuf, 4 * DM, 0, 0,  mlp_w2, 4 * DM, 0, 0,  out1, DM, 0, 0,
        mlp_b2, x2, DM, 4 * DM, 1.0f, 1);
}

// round 5
// speedup vs baseline: 2.8018x; 1.0914x over previous
#include <cuda_runtime.h>
#include <cuda_bf16.h>
#include <math.h>
#include <stdint.h>

#define BZ 4
#define TQ 1024
#define SK 1024
#define DM 1024
#define HH 16
#define HD 64

typedef unsigned short u16;
typedef uint32_t u32;

// ---------------------------------------------------------------------------
// Scratch (fp32)
// ---------------------------------------------------------------------------
__device__ float g_scores[(long long)BZ * HH * TQ * SK];
__device__ float g_x   [BZ * TQ * DM];
__device__ float g_x2  [BZ * TQ * DM];
__device__ float g_tv  [BZ * SK * DM];
__device__ float g_tvn [BZ * SK];

// ---------------------------------------------------------------------------
// Scratch (bf16 hi/lo split pairs)
// ---------------------------------------------------------------------------
__device__ u16 g_deh[BZ*TQ*DM],    g_del[BZ*TQ*DM];
__device__ u16 g_enh[BZ*SK*DM],    g_enl[BZ*SK*DM];
__device__ u16 g_qkvh[BZ*TQ*3*DM], g_qkvl[BZ*TQ*3*DM];
__device__ u16 g_ctxh[BZ*TQ*DM],   g_ctxl[BZ*TQ*DM];
__device__ u16 g_xh[BZ*TQ*DM],     g_xl[BZ*TQ*DM];
__device__ u16 g_q2h[BZ*TQ*DM],    g_q2l[BZ*TQ*DM];
__device__ u16 g_kv2h[BZ*SK*2*DM], g_kv2l[BZ*SK*2*DM];
__device__ u16 g_lnxh[BZ*TQ*DM],   g_lnxl[BZ*TQ*DM];
__device__ u16 g_hh[BZ*TQ*4*DM],   g_hl[BZ*TQ*4*DM];
__device__ u16 g_ph[(long long)BZ*HH*TQ*SK], g_pl[(long long)BZ*HH*TQ*SK];
// weights
__device__ u16 g_w1h[3*DM*DM],  g_w1l[3*DM*DM];
__device__ u16 g_wo1h[DM*DM],   g_wo1l[DM*DM];
__device__ u16 g_w2h[3*DM*DM],  g_w2l[3*DM*DM];
__device__ u16 g_wo2h[DM*DM],   g_wo2l[DM*DM];
__device__ u16 g_m1h[4*DM*DM],  g_m1l[4*DM*DM];
__device__ u16 g_m2h[4*DM*DM],  g_m2l[4*DM*DM];

// ---------------------------------------------------------------------------
// Primitives
// ---------------------------------------------------------------------------
__device__ __forceinline__ u32 smem_u32(const void* p) {
    u32 a;
    asm("{ .reg .u64 t; cvta.to.shared.u64 t, %1; cvt.u32.u64 %0, t; }" : "=r"(a) : "l"(p));
    return a;
}
__device__ __forceinline__ void ldsm_x4(u32 addr, u32* r) {
    asm volatile("ldmatrix.sync.aligned.m8n8.x4.shared.b16 {%0,%1,%2,%3}, [%4];"
        : "=r"(r[0]), "=r"(r[1]), "=r"(r[2]), "=r"(r[3]) : "r"(addr));
}
__device__ __forceinline__ void ldsm_x4_t(u32 addr, u32* r) {
    asm volatile("ldmatrix.sync.aligned.m8n8.x4.trans.shared.b16 {%0,%1,%2,%3}, [%4];"
        : "=r"(r[0]), "=r"(r[1]), "=r"(r[2]), "=r"(r[3]) : "r"(addr));
}
__device__ __forceinline__ void mma_bf16(float* c, const u32* a, const u32* b) {
    asm volatile("mma.sync.aligned.m16n8k16.row.col.f32.bf16.bf16.f32 "
        "{%0,%1,%2,%3}, {%4,%5,%6,%7}, {%8,%9}, {%0,%1,%2,%3};"
        : "+f"(c[0]), "+f"(c[1]), "+f"(c[2]), "+f"(c[3])
        : "r"(a[0]), "r"(a[1]), "r"(a[2]), "r"(a[3]), "r"(b[0]), "r"(b[1]));
}
__device__ __forceinline__ void split_bf16(float f, u16& h, u16& l) {
    __nv_bfloat16 bh = __float2bfloat16(f);
    float fl = f - __bfloat162float(bh);
    h = __bfloat16_as_ushort(bh);
    l = __bfloat16_as_ushort(__float2bfloat16(fl));
}
__device__ __forceinline__ u32 packhi2(float a, float b) {
    __nv_bfloat162 t = __floats2bfloat162_rn(a, b);
    return *reinterpret_cast<u32*>(&t);
}
__device__ __forceinline__ u32 packlo2(float a, float b) {
    float la = a - __bfloat162float(__float2bfloat16(a));
    float lb = b - __bfloat162float(__float2bfloat16(b));
    return packhi2(la, lb);
}

// ---------------------------------------------------------------------------
// Elementwise split: fp32 -> (hi, lo) bf16 arrays. n4 = n/4.
// ---------------------------------------------------------------------------
__global__ __launch_bounds__(256)
void split_kernel(const float* __restrict__ src, u16* __restrict__ hi,
                  u16* __restrict__ lo, int n4)
{
    int i = blockIdx.x * 256 + threadIdx.x;
    if (i >= n4) return;
    float4 v = ((const float4*)src)[i];
    u16 h0,h1,h2,h3,l0,l1,l2,l3;
    split_bf16(v.x,h0,l0); split_bf16(v.y,h1,l1);
    split_bf16(v.z,h2,l2); split_bf16(v.w,h3,l3);
    ((uint2*)hi)[i] = make_uint2((u32)h0 | ((u32)h1 << 16), (u32)h2 | ((u32)h3 << 16));
    ((uint2*)lo)[i] = make_uint2((u32)l0 | ((u32)l1 << 16), (u32)l2 | ((u32)l3 << 16));
}

// ---------------------------------------------------------------------------
// Reductions
// ---------------------------------------------------------------------------
__device__ __forceinline__ float block_sum(float v, float* sh) {
#pragma unroll
    for (int o = 16; o > 0; o >>= 1) v += __shfl_xor_sync(0xffffffffu, v, o);
    if ((threadIdx.x & 31) == 0) sh[threadIdx.x >> 5] = v;
    __syncthreads();
    if (threadIdx.x < 32) {
        float w = (threadIdx.x < 8) ? sh[threadIdx.x] : 0.0f;
#pragma unroll
        for (int o = 4; o > 0; o >>= 1) w += __shfl_xor_sync(0xffffffffu, w, o);
        if (threadIdx.x == 0) sh[0] = w;
    }
    __syncthreads();
    float r = sh[0];
    __syncthreads();
    return r;
}
__device__ __forceinline__ float block_max(float v, float* sh) {
#pragma unroll
    for (int o = 16; o > 0; o >>= 1) v = fmaxf(v, __shfl_xor_sync(0xffffffffu, v, o));
    if ((threadIdx.x & 31) == 0) sh[threadIdx.x >> 5] = v;
    __syncthreads();
    if (threadIdx.x < 32) {
        float w = (threadIdx.x < 8) ? sh[threadIdx.x] : -3.4e38f;
#pragma unroll
        for (int o = 4; o > 0; o >>= 1) w = fmaxf(w, __shfl_xor_sync(0xffffffffu, w, o));
        if (threadIdx.x == 0) sh[0] = w;
    }
    __syncthreads();
    float r = sh[0];
    __syncthreads();
    return r;
}

// ---------------------------------------------------------------------------
// LayerNorm emitting split bf16
// ---------------------------------------------------------------------------
__global__ __launch_bounds__(256)
void ln_split(const float* __restrict__ x, u16* __restrict__ yh, u16* __restrict__ yl,
              const float* __restrict__ g, const float* __restrict__ beta)
{
    __shared__ float sh[32];
    const long long row = blockIdx.x;
    const float* xr = x + row * DM;
    const int tid = threadIdx.x;
    float v[4];
    float s = 0.f, sq = 0.f;
#pragma unroll
    for (int i = 0; i < 4; i++) {
        float t = xr[tid + 256 * i];
        v[i] = t; s += t; sq += t * t;
    }
    s  = block_sum(s, sh);
    sq = block_sum(sq, sh);
    float mean = s * (1.0f / 1024.0f);
    float var  = fmaxf(sq * (1.0f / 1024.0f) - mean * mean, 0.0f);
    float inv  = rsqrtf(var + 1e-6f);
#pragma unroll
    for (int i = 0; i < 4; i++) {
        int c = tid + 256 * i;
        float y = (v[i] - mean) * inv * g[c] + beta[c];
        u16 h, l;
        split_bf16(y, h, l);
        yh[row * DM + c] = h;
        yl[row * DM + c] = l;
    }
}

// ---------------------------------------------------------------------------
// GEMM v3 (pre-split inputs): C = alpha*A@op(B) (+bias)(+gelu)(+res)
// 512 threads, 16 warps (4m x 4n), tile 128 x BN, BK=32.
// EF32: write fp32 C.  ESPL: write split C.
// ---------------------------------------------------------------------------
template<int BN, bool TRANSB, int ACT, bool EF32, bool ESPL>
__global__ __launch_bounds__(512, 1)
void gemm_bf(const u16* __restrict__ Ahg, const u16* __restrict__ Alg, int lda,
             long long Ab, long long Aho,
             const u16* __restrict__ Bhg, const u16* __restrict__ Blg, int ldb,
             long long Bb, long long Bho,
             float* __restrict__ Cf, u16* __restrict__ Chg, u16* __restrict__ Clg,
             int ldc, long long Cb, long long Cho,
             const float* __restrict__ bias,
             const float* __restrict__ res, int ldr,
             int K, float alpha, int nh)
{
    constexpr int PITCH = 40;
    constexpr int ASZ = 128 * PITCH;
    constexpr int BSZ = BN * PITCH;
    constexpr int STAGE = 2 * ASZ + 2 * BSZ;
    constexpr int WN = BN / 4;
    constexpr int NT = WN / 8;

    extern __shared__ __align__(128) u16 sm[];

    const int tid = threadIdx.x;
    const int lane = tid & 31;
    const int wid = tid >> 5;
    const int wm = (wid & 3) * 32;
    const int wn = (wid >> 2) * WN;

    const int bz = blockIdx.z;
    const int bb = bz / nh;
    const int hh = bz - bb * nh;
    const int m0 = blockIdx.y * 128;
    const int n0 = blockIdx.x * BN;

    const u16* Ah = Ahg + bb * Ab + hh * Aho + (long long)m0 * lda;
    const u16* Al = Alg + bb * Ab + hh * Aho + (long long)m0 * lda;
    const u16* Bh = Bhg + bb * Bb + hh * Bho + (TRANSB ? (long long)n0 * ldb : (long long)n0);
    const u16* Bl = Blg + bb * Bb + hh * Bho + (TRANSB ? (long long)n0 * ldb : (long long)n0);

    float acc[2][NT][4];
#pragma unroll
    for (int mi = 0; mi < 2; mi++)
#pragma unroll
        for (int ni = 0; ni < NT; ni++)
#pragma unroll
            for (int j = 0; j < 4; j++) acc[mi][ni][j] = 0.0f;

    const u32 sb0 = smem_u32(sm);
    const int nk = K >> 5;

    // A: 128x32 halves -> 512 uint4 per array; 1/thread. row=tid>>2, c8=tid&3.
    const int a_row = tid >> 2, a_c8 = tid & 3;
    // B trans (BN=128): same mapping. BN=64 trans unused.
    // B non-trans: 32 x BN halves.
    const int bt_row = tid >> 2, bt_c8 = tid & 3;
    const int bn_kr = (BN == 128) ? (tid >> 4) : (tid >> 3);
    const int bn_nc8 = (BN == 128) ? (tid & 15) : (tid & 7);

    uint4 rah, ral, rbh, rbl;

    auto loadA = [&](int k0) {
        const long long o = (long long)a_row * lda + k0 + a_c8 * 8;
        rah = *(const uint4*)(Ah + o);
        ral = *(const uint4*)(Al + o);
    };
    auto loadB = [&](int k0) {
        if (TRANSB) {
            const long long o = (long long)bt_row * ldb + k0 + bt_c8 * 8;
            rbh = *(const uint4*)(Bh + o);
            rbl = *(const uint4*)(Bl + o);
        } else {
            if (BN == 128 || tid < 256) {
                const long long o = (long long)(k0 + bn_kr) * ldb + bn_nc8 * 8;
                rbh = *(const uint4*)(Bh + o);
                rbl = *(const uint4*)(Bl + o);
            }
        }
    };
    auto storeStage = [&](int buf) {
        u16* sAh = sm + buf * STAGE;
        u16* sAl = sAh + ASZ;
        u16* sBh = sAl + ASZ;
        u16* sBl = sBh + BSZ;
        {
            int off = a_row * PITCH + a_c8 * 8;
            *(uint4*)(sAh + off) = rah;
            *(uint4*)(sAl + off) = ral;
        }
        if (TRANSB) {
            int off = bt_row * PITCH + bt_c8 * 8;
            *(uint4*)(sBh + off) = rbh;
            *(uint4*)(sBl + off) = rbl;
        } else {
            if (BN == 128 || tid < 256) {
                const u16* ph = (const u16*)&rbh;
                const u16* pl = (const u16*)&rbl;
#pragma unroll
                for (int j = 0; j < 8; j++) {
                    int off = (bn_nc8 * 8 + j) * PITCH + bn_kr;
                    sBh[off] = ph[j];
                    sBl[off] = pl[j];
                }
            }
        }
    };

    loadA(0); loadB(0);
    storeStage(0);
    __syncthreads();

    for (int k = 0; k < nk; k++) {
        const int buf = k & 1;
        if (k + 1 < nk) { loadA((k + 1) << 5); loadB((k + 1) << 5); }

        u32 base = sb0 + (u32)buf * STAGE * 2;
#pragma unroll
        for (int kk = 0; kk < 32; kk += 16) {
            u32 ah[2][4], al_[2][4];
            int arow = wm + (lane & 15);
            int acol = kk + ((lane >> 4) << 3);
#pragma unroll
            for (int mi = 0; mi < 2; mi++) {
                u32 ad = base + (u32)((((arow + mi * 16) * PITCH) + acol) * 2);
                ldsm_x4(ad, ah[mi]);
                ldsm_x4(ad + ASZ * 2, al_[mi]);
            }
            u32 bh_[NT][2], bl_[NT][2];
            int brow = wn + (lane & 7) + ((lane & 16) >> 1);
            int bcol = kk + (((lane >> 3) & 1) << 3);
#pragma unroll
            for (int nj = 0; nj < NT / 2; nj++) {
                u32 bd = base + (u32)((2 * ASZ + (brow + nj * 16) * PITCH + bcol) * 2);
                u32 r[4];
                ldsm_x4(bd, r);
                bh_[2 * nj][0] = r[0]; bh_[2 * nj][1] = r[1];
                bh_[2 * nj + 1][0] = r[2]; bh_[2 * nj + 1][1] = r[3];
                ldsm_x4(bd + BSZ * 2, r);
                bl_[2 * nj][0] = r[0]; bl_[2 * nj][1] = r[1];
                bl_[2 * nj + 1][0] = r[2]; bl_[2 * nj + 1][1] = r[3];
            }
#pragma unroll
            for (int mi = 0; mi < 2; mi++)
#pragma unroll
                for (int ni = 0; ni < NT; ni++) {
                    mma_bf16(acc[mi][ni], ah[mi], bh_[ni]);
                    mma_bf16(acc[mi][ni], ah[mi], bl_[ni]);
                    mma_bf16(acc[mi][ni], al_[mi], bh_[ni]);
                }
        }
        if (k + 1 < nk) storeStage(buf ^ 1);
        __syncthreads();
    }

    // epilogue
    float* Cfg = EF32 ? (Cf + bb * Cb + hh * Cho) : nullptr;
    u16* Chh = ESPL ? (Chg + bb * Cb + hh * Cho) : nullptr;
    u16* Cll = ESPL ? (Clg + bb * Cb + hh * Cho) : nullptr;
#pragma unroll
    for (int mi = 0; mi < 2; mi++) {
#pragma unroll
        for (int ni = 0; ni < NT; ni++) {
            int m = m0 + wm + mi * 16 + (lane >> 2);
            int n = n0 + wn + ni * 8 + (lane & 3) * 2;
#pragma unroll
            for (int rr = 0; rr < 2; rr++) {
                int mm = m + rr * 8;
                float v0 = acc[mi][ni][rr * 2 + 0] * alpha;
                float v1 = acc[mi][ni][rr * 2 + 1] * alpha;
                if (bias) { v0 += bias[n]; v1 += bias[n + 1]; }
                if (ACT == 1) {
                    v0 = 0.5f * v0 * (1.0f + erff(v0 * 0.70710678118654752f));
                    v1 = 0.5f * v1 * (1.0f + erff(v1 * 0.70710678118654752f));
                }
                if (res) {
                    v0 += res[(long long)mm * ldr + n];
                    v1 += res[(long long)mm * ldr + n + 1];
                }
                long long co = (long long)mm * ldc + n;
                if (EF32) *(float2*)(Cfg + co) = make_float2(v0, v1);
                if (ESPL) {
                    *(u32*)(Chh + co) = packhi2(v0, v1);
                    *(u32*)(Cll + co) = packlo2(v0, v1);
                }
            }
        }
    }
}

// ---------------------------------------------------------------------------
// Flash self-attention on pre-split QKV; emits split ctx.
// 128 threads, 4 warps, 64 q-rows per CTA, 64-key chunks, causal skip.
// ---------------------------------------------------------------------------
__global__ __launch_bounds__(128)
void flash_self(const u16* __restrict__ qh, const u16* __restrict__ ql,
                const unsigned char* __restrict__ kpm,
                u16* __restrict__ ch, u16* __restrict__ cl)
{
    constexpr int P = 72;
    constexpr int TSZ = 64 * P;
    extern __shared__ __align__(128) u16 fs[];
    u16* sQh = fs;
    u16* sQl = sQh + TSZ;
    u16* sKh = sQl + TSZ;
    u16* sKl = sKh + TSZ;
    u16* sVh = sKl + TSZ;
    u16* sVl = sVh + TSZ;
    unsigned char* smask = (unsigned char*)(sVl + TSZ);

    const int tid = threadIdx.x, lane = tid & 31, wid = tid >> 5;
    const int bx = blockIdx.x;
    const int bh = blockIdx.y;
    const int b = bh >> 4, h = bh & 15;
    const int t0 = bx * 64;

    const long long qoff = ((long long)b * TQ + t0) * 3 * DM + h * HD;
    const long long koff = ((long long)b * TQ) * 3 * DM + DM + h * HD;
    const long long voff = ((long long)b * TQ) * 3 * DM + 2 * DM + h * HD;
    const unsigned char* kp = kpm + (long long)b * SK;

    // Q tile: 512 uint4 per array, 4/thread
#pragma unroll
    for (int u = 0; u < 4; u++) {
        int idx = tid + u * 128;
        int r = idx >> 3, c8 = idx & 7;
        long long o = qoff + (long long)r * 3 * DM + c8 * 8;
        int off = r * P + c8 * 8;
        *(uint4*)(sQh + off) = *(const uint4*)(qh + o);
        *(uint4*)(sQl + off) = *(const uint4*)(ql + o);
    }

    float o_[8][4];
#pragma unroll
    for (int i = 0; i < 8; i++)
#pragma unroll
        for (int j = 0; j < 4; j++) o_[i][j] = 0.0f;
    float mrow0 = -1e30f, mrow1 = -1e30f, lrow0 = 0.0f, lrow1 = 0.0f;

    const u32 qb = smem_u32(sQh);
    const u32 kb = smem_u32(sKh);
    const u32 vb = smem_u32(sVh);

    const int nch = bx + 1;
    for (int ch_i = 0; ch_i < nch; ch_i++) {
        const int s0 = ch_i * 64;
        __syncthreads();
#pragma unroll
        for (int u = 0; u < 4; u++) {
            int idx = tid + u * 128;
            int r = idx >> 3, c8 = idx & 7;
            long long ko = koff + (long long)(s0 + r) * 3 * DM + c8 * 8;
            long long vo = voff + (long long)(s0 + r) * 3 * DM + c8 * 8;
            int off = r * P + c8 * 8;
            *(uint4*)(sKh + off) = *(const uint4*)(qh + ko);
            *(uint4*)(sKl + off) = *(const uint4*)(ql + ko);
            *(uint4*)(sVh + off) = *(const uint4*)(qh + vo);
            *(uint4*)(sVl + off) = *(const uint4*)(ql + vo);
        }
        if (tid < 64) smask[tid] = kp[s0 + tid];
        __syncthreads();

        // S = 0.125 Q K^T
        float sc[8][4];
#pragma unroll
        for (int i = 0; i < 8; i++)
#pragma unroll
            for (int j = 0; j < 4; j++) sc[i][j] = 0.0f;

#pragma unroll
        for (int kt = 0; kt < 4; kt++) {
            u32 aq[4], al_[4];
            u32 ad = qb + (u32)(((wid * 16 + (lane & 15)) * P + kt * 16 + ((lane >> 4) << 3)) * 2);
            ldsm_x4(ad, aq);
            ldsm_x4(ad + TSZ * 2, al_);
            u32 bh_[8][2], bl_[8][2];
#pragma unroll
            for (int nj = 0; nj < 4; nj++) {
                u32 bd = kb + (u32)(((nj * 16 + (lane & 7) + ((lane & 16) >> 1)) * P
                                    + kt * 16 + (((lane >> 3) & 1) << 3)) * 2);
                u32 r[4];
                ldsm_x4(bd, r);
                bh_[2*nj][0]=r[0]; bh_[2*nj][1]=r[1]; bh_[2*nj+1][0]=r[2]; bh_[2*nj+1][1]=r[3];
                ldsm_x4(bd + TSZ * 2, r);
                bl_[2*nj][0]=r[0]; bl_[2*nj][1]=r[1]; bl_[2*nj+1][0]=r[2]; bl_[2*nj+1][1]=r[3];
            }
#pragma unroll
            for (int ni = 0; ni < 8; ni++) {
                mma_bf16(sc[ni], aq, bh_[ni]);
                mma_bf16(sc[ni], aq, bl_[ni]);
                mma_bf16(sc[ni], al_, bh_[ni]);
            }
        }

        const int gr0 = t0 + wid * 16 + (lane >> 2);
#pragma unroll
        for (int ni = 0; ni < 8; ni++) {
#pragma unroll
            for (int j = 0; j < 4; j++) {
                int rr = gr0 + ((j >> 1) << 3);
                int cl_ = ni * 8 + (lane & 3) * 2 + (j & 1);
                float xv = sc[ni][j] * 0.125f;
                if (s0 + cl_ > rr) xv -= 1e9f;
                if (smask[cl_]) xv = -1e9f;
                sc[ni][j] = xv;
            }
        }

        float mc0 = -1e30f, mc1 = -1e30f;
#pragma unroll
        for (int ni = 0; ni < 8; ni++) {
            mc0 = fmaxf(mc0, fmaxf(sc[ni][0], sc[ni][1]));
            mc1 = fmaxf(mc1, fmaxf(sc[ni][2], sc[ni][3]));
        }
#pragma unroll
        for (int off = 1; off <= 2; off <<= 1) {
            mc0 = fmaxf(mc0, __shfl_xor_sync(0xffffffffu, mc0, off));
            mc1 = fmaxf(mc1, __shfl_xor_sync(0xffffffffu, mc1, off));
        }
        float mn0 = fmaxf(mrow0, mc0), mn1 = fmaxf(mrow1, mc1);
        float scale0 = __expf(mrow0 - mn0), scale1 = __expf(mrow1 - mn1);
        float ls0 = 0.0f, ls1 = 0.0f;
#pragma unroll
        for (int ni = 0; ni < 8; ni++) {
            sc[ni][0] = __expf(sc[ni][0] - mn0);
            sc[ni][1] = __expf(sc[ni][1] - mn0);
            sc[ni][2] = __expf(sc[ni][2] - mn1);
            sc[ni][3] = __expf(sc[ni][3] - mn1);
            ls0 += sc[ni][0] + sc[ni][1];
            ls1 += sc[ni][2] + sc[ni][3];
        }
#pragma unroll
        for (int off = 1; off <= 2; off <<= 1) {
            ls0 += __shfl_xor_sync(0xffffffffu, ls0, off);
            ls1 += __shfl_xor_sync(0xffffffffu, ls1, off);
        }
        lrow0 = lrow0 * scale0 + ls0;
        lrow1 = lrow1 * scale1 + ls1;
        mrow0 = mn0; mrow1 = mn1;
#pragma unroll
        for (int ni = 0; ni < 8; ni++) {
            o_[ni][0] *= scale0; o_[ni][1] *= scale0;
            o_[ni][2] *= scale1; o_[ni][3] *= scale1;
        }

#pragma unroll
        for (int kt = 0; kt < 4; kt++) {
            u32 ph[4], pl[4];
            ph[0] = packhi2(sc[2*kt][0],   sc[2*kt][1]);
            ph[1] = packhi2(sc[2*kt][2],   sc[2*kt][3]);
            ph[2] = packhi2(sc[2*kt+1][0], sc[2*kt+1][1]);
            ph[3] = packhi2(sc[2*kt+1][2], sc[2*kt+1][3]);
            pl[0] = packlo2(sc[2*kt][0],   sc[2*kt][1]);
            pl[1] = packlo2(sc[2*kt][2],   sc[2*kt][3]);
            pl[2] = packlo2(sc[2*kt+1][0], sc[2*kt+1][1]);
            pl[3] = packlo2(sc[2*kt+1][2], sc[2*kt+1][3]);

            u32 vh_[8][2], vl_[8][2];
#pragma unroll
            for (int nj = 0; nj < 4; nj++) {
                u32 bd = vb + (u32)(((kt * 16 + (lane & 15)) * P
                                    + nj * 16 + ((lane >> 4) << 3)) * 2);
                u32 r[4];
                ldsm_x4_t(bd, r);
                vh_[2*nj][0]=r[0]; vh_[2*nj][1]=r[1]; vh_[2*nj+1][0]=r[2]; vh_[2*nj+1][1]=r[3];
                ldsm_x4_t(bd + TSZ * 2, r);
                vl_[2*nj][0]=r[0]; vl_[2*nj][1]=r[1]; vl_[2*nj+1][0]=r[2]; vl_[2*nj+1][1]=r[3];
            }
#pragma unroll
            for (int ni = 0; ni < 8; ni++) {
                mma_bf16(o_[ni], ph, vh_[ni]);
                mma_bf16(o_[ni], ph, vl_[ni]);
                mma_bf16(o_[ni], pl, vh_[ni]);
            }
        }
    }

    float inv0 = 1.0f / fmaxf(lrow0, 1e-30f);
    float inv1 = 1.0f / fmaxf(lrow1, 1e-30f);
    const long long cbase = ((long long)b * TQ) * DM + h * HD;
    const int r0 = t0 + wid * 16 + (lane >> 2);
#pragma unroll
    for (int ni = 0; ni < 8; ni++) {
        int c = ni * 8 + (lane & 3) * 2;
        long long o0 = cbase + (long long)r0 * DM + c;
        long long o1 = cbase + (long long)(r0 + 8) * DM + c;
        *(u32*)(ch + o0) = packhi2(o_[ni][0] * inv0, o_[ni][1] * inv0);
        *(u32*)(cl + o0) = packlo2(o_[ni][0] * inv0, o_[ni][1] * inv0);
        *(u32*)(ch + o1) = packhi2(o_[ni][2] * inv1, o_[ni][3] * inv1);
        *(u32*)(cl + o1) = packlo2(o_[ni][2] * inv1, o_[ni][3] * inv1);
    }
}

// ---------------------------------------------------------------------------
// Fused cross softmax: per (t, b), loop 16 heads; write split probs + out2.
// ---------------------------------------------------------------------------
__global__ __launch_bounds__(256)
void softmax_fused(const float* __restrict__ sc, const unsigned char* __restrict__ kpm,
                   const float* __restrict__ tvn,
                   u16* __restrict__ ph, u16* __restrict__ pl, float* __restrict__ out2)
{
    __shared__ float sh[32];
    __shared__ unsigned char km[SK];
    const int t = blockIdx.x, b = blockIdx.y;
    const int tid = threadIdx.x;
    for (int i = tid; i < SK; i += 256) km[i] = kpm[(long long)b * SK + i];
    __syncthreads();

    float psum[4] = {0.f, 0.f, 0.f, 0.f};
    for (int h = 0; h < HH; h++) {
        const long long roff = (((long long)(b * HH + h)) * TQ + t) * SK;
        const float* row = sc + roff;
        float v[4];
        float mx = -3.4e38f;
#pragma unroll
        for (int i = 0; i < 4; i++) {
            int s = tid + 256 * i;
            float x = row[s];
            if (km[s]) x = -1e9f;
            v[i] = x;
            mx = fmaxf(mx, x);
        }
        mx = block_max(mx, sh);
        float sum = 0.f;
#pragma unroll
        for (int i = 0; i < 4; i++) {
            v[i] = __expf(v[i] - mx);
            sum += v[i];
        }
        sum = block_sum(sum, sh);
        float inv = 1.0f / sum;
#pragma unroll
        for (int i = 0; i < 4; i++) {
            int s = tid + 256 * i;
            float p = v[i] * inv;
            psum[i] += p;
            u16 hb, lb;
            split_bf16(p, hb, lb);
            ph[roff + s] = hb;
            pl[roff + s] = lb;
        }
    }
#pragma unroll
    for (int i = 0; i < 4; i++) {
        int s = tid + 256 * i;
        out2[((long long)b * TQ + t) * SK + s] = psum[i] * (1.0f / 16.0f) * tvn[b * SK + s];
    }
}

// ---------------------------------------------------------------------------
// Row L2 norm
// ---------------------------------------------------------------------------
__global__ __launch_bounds__(256)
void rownorm_kernel(const float* __restrict__ x, float* __restrict__ out)
{
    __shared__ float sh[32];
    const long long row = blockIdx.x;
    const float* xr = x + row * DM;
    float sq = 0.f;
#pragma unroll
    for (int i = 0; i < 4; i++) {
        float t = xr[threadIdx.x + 256 * i];
        sq += t * t;
    }
    sq = block_sum(sq, sh);
    if (threadIdx.x == 0) out[row] = sqrtf(sq);
}

// ---------------------------------------------------------------------------
// Host launcher
// ---------------------------------------------------------------------------
extern "C" void kernel_launch(void* const* d_in, const int* in_sizes, int n_in,
                              void* d_out, int out_size)
{
    const float* dec_in  = (const float*)d_in[0];
    const float* enc_out = (const float*)d_in[1];
    const unsigned char* en_mask = (const unsigned char*)d_in[2];
    const unsigned char* de_mask = (const unsigned char*)d_in[3];
    const float* ln_g   = (const float*)d_in[4];
    const float* ln_b   = (const float*)d_in[5];
    const float* w_in1  = (const float*)d_in[6];
    const float* b_in1  = (const float*)d_in[7];
    const float* w_out1 = (const float*)d_in[8];
    const float* b_out1 = (const float*)d_in[9];
    const float* w_in2  = (const float*)d_in[10];
    const float* b_in2  = (const float*)d_in[11];
    const float* w_out2 = (const float*)d_in[12];
    const float* b_out2 = (const float*)d_in[13];
    const float* mlp_w1 = (const float*)d_in[14];
    const float* mlp_b1 = (const float*)d_in[15];
    const float* mlp_w2 = (const float*)d_in[16];
    const float* mlp_b2 = (const float*)d_in[17];

    float *scores, *x, *x2, *tv, *tvn;
    cudaGetSymbolAddress((void**)&scores, g_scores);
    cudaGetSymbolAddress((void**)&x,  g_x);
    cudaGetSymbolAddress((void**)&x2, g_x2);
    cudaGetSymbolAddress((void**)&tv, g_tv);
    cudaGetSymbolAddress((void**)&tvn, g_tvn);

    u16 *deh,*del,*enh,*enl,*qkvh,*qkvl,*ctxh,*ctxl,*xh,*xl,*q2h,*q2l,*kv2h,*kv2l;
    u16 *lnxh,*lnxl,*hhp,*hlp,*ph,*pl;
    u16 *w1h,*w1l,*wo1h,*wo1l,*w2h,*w2l,*wo2h,*wo2l,*m1h,*m1l,*m2h,*m2l;
    cudaGetSymbolAddress((void**)&deh, g_deh);   cudaGetSymbolAddress((void**)&del, g_del);
    cudaGetSymbolAddress((void**)&enh, g_enh);   cudaGetSymbolAddress((void**)&enl, g_enl);
    cudaGetSymbolAddress((void**)&qkvh, g_qkvh); cudaGetSymbolAddress((void**)&qkvl, g_qkvl);
    cudaGetSymbolAddress((void**)&ctxh, g_ctxh); cudaGetSymbolAddress((void**)&ctxl, g_ctxl);
    cudaGetSymbolAddress((void**)&xh, g_xh);     cudaGetSymbolAddress((void**)&xl, g_xl);
    cudaGetSymbolAddress((void**)&q2h, g_q2h);   cudaGetSymbolAddress((void**)&q2l, g_q2l);
    cudaGetSymbolAddress((void**)&kv2h, g_kv2h); cudaGetSymbolAddress((void**)&kv2l, g_kv2l);
    cudaGetSymbolAddress((void**)&lnxh, g_lnxh); cudaGetSymbolAddress((void**)&lnxl, g_lnxl);
    cudaGetSymbolAddress((void**)&hhp, g_hh);    cudaGetSymbolAddress((void**)&hlp, g_hl);
    cudaGetSymbolAddress((void**)&ph, g_ph);     cudaGetSymbolAddress((void**)&pl, g_pl);
    cudaGetSymbolAddress((void**)&w1h, g_w1h);   cudaGetSymbolAddress((void**)&w1l, g_w1l);
    cudaGetSymbolAddress((void**)&wo1h, g_wo1h); cudaGetSymbolAddress((void**)&wo1l, g_wo1l);
    cudaGetSymbolAddress((void**)&w2h, g_w2h);   cudaGetSymbolAddress((void**)&w2l, g_w2l);
    cudaGetSymbolAddress((void**)&wo2h, g_wo2h); cudaGetSymbolAddress((void**)&wo2l, g_wo2l);
    cudaGetSymbolAddress((void**)&m1h, g_m1h);   cudaGetSymbolAddress((void**)&m1l, g_m1l);
    cudaGetSymbolAddress((void**)&m2h, g_m2h);   cudaGetSymbolAddress((void**)&m2l, g_m2l);

    float* out1 = (float*)d_out;
    float* out2 = (float*)d_out + (long long)BZ * TQ * DM;

    const int BT = BZ * TQ;
    const long long TSh = (long long)TQ * SK;
    const long long TSb = (long long)HH * TQ * SK;

    const int SM128 = 2 * (2 * 128 * 40 + 2 * 128 * 40) * 2; // 81920 B
    const int SM64  = 2 * (2 * 128 * 40 + 2 * 64 * 40) * 2;  // 61440 B
    const int SMFL  = 6 * 64 * 72 * 2 + 128;
    cudaFuncSetAttribute(gemm_bf<128,true ,0,false,true >, cudaFuncAttributeMaxDynamicSharedMemorySize, SM128);
    cudaFuncSetAttribute(gemm_bf<128,true ,0,true ,true >, cudaFuncAttributeMaxDynamicSharedMemorySize, SM128);
    cudaFuncSetAttribute(gemm_bf<128,true ,0,true ,false>, cudaFuncAttributeMaxDynamicSharedMemorySize, SM128);
    cudaFuncSetAttribute(gemm_bf<128,false,0,true ,false>, cudaFuncAttributeMaxDynamicSharedMemorySize, SM128);
    cudaFuncSetAttribute(gemm_bf<64 ,false,0,false,true >, cudaFuncAttributeMaxDynamicSharedMemorySize, SM64);
    cudaFuncSetAttribute(gemm_bf<128,true ,1,false,true >, cudaFuncAttributeMaxDynamicSharedMemorySize, SM128);
    cudaFuncSetAttribute(flash_self, cudaFuncAttributeMaxDynamicSharedMemorySize, SMFL);

    // 0: split weights
    split_kernel<<<(3*DM*DM/4 + 255)/256, 256>>>(w_in1,  w1h,  w1l,  3*DM*DM/4);
    split_kernel<<<(DM*DM/4   + 255)/256, 256>>>(w_out1, wo1h, wo1l, DM*DM/4);
    split_kernel<<<(3*DM*DM/4 + 255)/256, 256>>>(w_in2,  w2h,  w2l,  3*DM*DM/4);
    split_kernel<<<(DM*DM/4   + 255)/256, 256>>>(w_out2, wo2h, wo2l, DM*DM/4);
    split_kernel<<<(4*DM*DM/4 + 255)/256, 256>>>(mlp_w1, m1h,  m1l,  4*DM*DM/4);
    split_kernel<<<(4*DM*DM/4 + 255)/256, 256>>>(mlp_w2, m2h,  m2l,  4*DM*DM/4);

    // 1-2: LayerNorms -> split
    ln_split<<<BT, 256>>>(dec_in, deh, del, ln_g, ln_b);
    ln_split<<<BT, 256>>>(enc_out, enh, enl, ln_g, ln_b);

    // 3: QKV1 -> split
    gemm_bf<128,true,0,false,true><<<dim3(3*DM/128, BT/128, 1), 512, SM128>>>(
        deh, del, DM, 0, 0,  w1h, w1l, DM, 0, 0,
        nullptr, qkvh, qkvl, 3*DM, 0, 0,
        b_in1, nullptr, 0, DM, 1.0f, 1);

    // 4: flash self-attention -> ctx split
    flash_self<<<dim3(TQ/64, BZ*HH), 128, SMFL>>>(qkvh, qkvl, de_mask, ctxh, ctxl);

    // 5: x = dec_in + ctx @ w_out1^T + b_out1  (fp32 + split)
    gemm_bf<128,true,0,true,true><<<dim3(DM/128, BT/128, 1), 512, SM128>>>(
        ctxh, ctxl, DM, 0, 0,  wo1h, wo1l, DM, 0, 0,
        x, xh, xl, DM, 0, 0,
        b_out1, dec_in, DM, DM, 1.0f, 1);

    // 6: q2 -> split
    gemm_bf<128,true,0,false,true><<<dim3(DM/128, BT/128, 1), 512, SM128>>>(
        xh, xl, DM, 0, 0,  w2h, w2l, DM, 0, 0,
        nullptr, q2h, q2l, DM, 0, 0,
        b_in2, nullptr, 0, DM, 1.0f, 1);

    // 7: kv2 -> split
    gemm_bf<128,true,0,false,true><<<dim3(2*DM/128, BT/128, 1), 512, SM128>>>(
        enh, enl, DM, 0, 0,  w2h + (long long)DM*DM, w2l + (long long)DM*DM, DM, 0, 0,
        nullptr, kv2h, kv2l, 2*DM, 0, 0,
        b_in2 + DM, nullptr, 0, DM, 1.0f, 1);

    // 8: tv = en_out @ w_out2 (non-trans) -> fp32 ; 9: rownorm
    gemm_bf<128,false,0,true,false><<<dim3(DM/128, BT/128, 1), 512, SM128>>>(
        enh, enl, DM, 0, 0,  wo2h, wo2l, DM, 0, 0,
        tv, nullptr, nullptr, DM, 0, 0,
        nullptr, nullptr, 0, DM, 1.0f, 1);
    rownorm_kernel<<<BT, 256>>>(tv, tvn);

    // 10: cross scores -> fp32
    gemm_bf<128,true,0,true,false><<<dim3(SK/128, TQ/128, BZ*HH), 512, SM128>>>(
        q2h, q2l, DM, (long long)TQ*DM, HD,
        kv2h, kv2l, 2*DM, (long long)SK*2*DM, HD,
        scores, nullptr, nullptr, SK, TSb, TSh,
        nullptr, nullptr, 0, HD, 0.125f, HH);

    // 11: fused softmax: probs split + out2
    softmax_fused<<<dim3(TQ, BZ), 256>>>(scores, en_mask, tvn, ph, pl, out2);

    // 12: ctx = probs @ V2 -> split
    gemm_bf<64,false,0,false,true><<<dim3(1, TQ/128, BZ*HH), 512, SM64>>>(
        ph, pl, SK, TSb, TSh,
        kv2h + DM, kv2l + DM, 2*DM, (long long)SK*2*DM, HD,
        nullptr, ctxh, ctxl, DM, (long long)TQ*DM, HD,
        nullptr, nullptr, 0, SK, 1.0f, HH);

    // 13: x2 = x + ctx @ w_out2^T + b_out2 -> fp32
    gemm_bf<128,true,0,true,false><<<dim3(DM/128, BT/128, 1), 512, SM128>>>(
        ctxh, ctxl, DM, 0, 0,  wo2h, wo2l, DM, 0, 0,
        x2, nullptr, nullptr, DM, 0, 0,
        b_out2, x, DM, DM, 1.0f, 1);

    // 14: lnx -> split
    ln_split<<<BT, 256>>>(x2, lnxh, lnxl, ln_g, ln_b);

    // 15: h = gelu(lnx @ mlp_w1^T + b1) -> split
    gemm_bf<128,true,1,false,true><<<dim3(4*DM/128, BT/128, 1), 512, SM128>>>(
        lnxh, lnxl, DM, 0, 0,  m1h, m1l, DM, 0, 0,
        nullptr, hhp, hlp, 4*DM, 0, 0,
        mlp_b1, nullptr, 0, DM, 1.0f, 1);

    // 16: out1 = x2 + h @ mlp_w2^T + b2
    gemm_bf<128,true,0,true,false><<<dim3(DM/128, BT/128, 1), 512, SM128>>>(
        hhp, hlp, 4*DM, 0, 0,  m2h, m2l, 4*DM, 0, 0,
        out1, nullptr, nullptr, DM, 0, 0,
        mlp_b2, x2, DM, 4*DM, 1.0f, 1);
}

// round 6
// speedup vs baseline: 3.1106x; 1.1102x over previous
#include <cuda_runtime.h>
#include <cuda_bf16.h>
#include <math.h>
#include <stdint.h>

#define BZ 4
#define TQ 1024
#define SK 1024
#define DM 1024
#define HH 16
#define HD 64

typedef unsigned short u16;
typedef uint32_t u32;

// ---------------------------------------------------------------------------
// Scratch (fp32)
// ---------------------------------------------------------------------------
__device__ float g_scores[(long long)BZ * HH * TQ * SK];
__device__ float g_x   [BZ * TQ * DM];
__device__ float g_x2  [BZ * TQ * DM];
__device__ float g_tv  [BZ * SK * DM];
__device__ float g_tvn [BZ * SK];

// ---------------------------------------------------------------------------
// Scratch (bf16 hi/lo split pairs)
// ---------------------------------------------------------------------------
__device__ u16 g_deh[BZ*TQ*DM],    g_del[BZ*TQ*DM];
__device__ u16 g_enh[BZ*SK*DM],    g_enl[BZ*SK*DM];
__device__ u16 g_qkvh[BZ*TQ*3*DM], g_qkvl[BZ*TQ*3*DM];
__device__ u16 g_ctxh[BZ*TQ*DM],   g_ctxl[BZ*TQ*DM];
__device__ u16 g_xh[BZ*TQ*DM],     g_xl[BZ*TQ*DM];
__device__ u16 g_q2h[BZ*TQ*DM],    g_q2l[BZ*TQ*DM];
__device__ u16 g_kv2h[BZ*SK*2*DM], g_kv2l[BZ*SK*2*DM];
__device__ u16 g_lnxh[BZ*TQ*DM],   g_lnxl[BZ*TQ*DM];
__device__ u16 g_hh[BZ*TQ*4*DM],   g_hl[BZ*TQ*4*DM];
__device__ u16 g_ph[(long long)BZ*HH*TQ*SK], g_pl[(long long)BZ*HH*TQ*SK];
// weights
__device__ u16 g_w1h[3*DM*DM],  g_w1l[3*DM*DM];
__device__ u16 g_wo1h[DM*DM],   g_wo1l[DM*DM];
__device__ u16 g_w2h[3*DM*DM],  g_w2l[3*DM*DM];
__device__ u16 g_wo2h[DM*DM],   g_wo2l[DM*DM];
__device__ u16 g_m1h[4*DM*DM],  g_m1l[4*DM*DM];
__device__ u16 g_m2h[4*DM*DM],  g_m2l[4*DM*DM];

// ---------------------------------------------------------------------------
// Primitives
// ---------------------------------------------------------------------------
__device__ __forceinline__ u32 smem_u32(const void* p) {
    u32 a;
    asm("{ .reg .u64 t; cvta.to.shared.u64 t, %1; cvt.u32.u64 %0, t; }" : "=r"(a) : "l"(p));
    return a;
}
__device__ __forceinline__ void ldsm_x4(u32 addr, u32* r) {
    asm volatile("ldmatrix.sync.aligned.m8n8.x4.shared.b16 {%0,%1,%2,%3}, [%4];"
        : "=r"(r[0]), "=r"(r[1]), "=r"(r[2]), "=r"(r[3]) : "r"(addr));
}
__device__ __forceinline__ void ldsm_x4_t(u32 addr, u32* r) {
    asm volatile("ldmatrix.sync.aligned.m8n8.x4.trans.shared.b16 {%0,%1,%2,%3}, [%4];"
        : "=r"(r[0]), "=r"(r[1]), "=r"(r[2]), "=r"(r[3]) : "r"(addr));
}
__device__ __forceinline__ void mma_bf16(float* c, const u32* a, const u32* b) {
    asm volatile("mma.sync.aligned.m16n8k16.row.col.f32.bf16.bf16.f32 "
        "{%0,%1,%2,%3}, {%4,%5,%6,%7}, {%8,%9}, {%0,%1,%2,%3};"
        : "+f"(c[0]), "+f"(c[1]), "+f"(c[2]), "+f"(c[3])
        : "r"(a[0]), "r"(a[1]), "r"(a[2]), "r"(a[3]), "r"(b[0]), "r"(b[1]));
}
#define CP_ASYNC16(dst, src) \
    asm volatile("cp.async.cg.shared.global [%0], [%1], 16;" :: "r"(dst), "l"(src))
#define CP_COMMIT() asm volatile("cp.async.commit_group;" ::: "memory")
#define CP_WAIT(n)  asm volatile("cp.async.wait_group %0;" :: "n"(n) : "memory")

__device__ __forceinline__ void split_bf16(float f, u16& h, u16& l) {
    __nv_bfloat16 bh = __float2bfloat16(f);
    float fl = f - __bfloat162float(bh);
    h = __bfloat16_as_ushort(bh);
    l = __bfloat16_as_ushort(__float2bfloat16(fl));
}
__device__ __forceinline__ u32 packhi2(float a, float b) {
    __nv_bfloat162 t = __floats2bfloat162_rn(a, b);
    return *reinterpret_cast<u32*>(&t);
}
__device__ __forceinline__ u32 packlo2(float a, float b) {
    float la = a - __bfloat162float(__float2bfloat16(a));
    float lb = b - __bfloat162float(__float2bfloat16(b));
    return packhi2(la, lb);
}

// ---------------------------------------------------------------------------
// Elementwise split
// ---------------------------------------------------------------------------
__global__ __launch_bounds__(256)
void split_kernel(const float* __restrict__ src, u16* __restrict__ hi,
                  u16* __restrict__ lo, int n4)
{
    int i = blockIdx.x * 256 + threadIdx.x;
    if (i >= n4) return;
    float4 v = ((const float4*)src)[i];
    u16 h0,h1,h2,h3,l0,l1,l2,l3;
    split_bf16(v.x,h0,l0); split_bf16(v.y,h1,l1);
    split_bf16(v.z,h2,l2); split_bf16(v.w,h3,l3);
    ((uint2*)hi)[i] = make_uint2((u32)h0 | ((u32)h1 << 16), (u32)h2 | ((u32)h3 << 16));
    ((uint2*)lo)[i] = make_uint2((u32)l0 | ((u32)l1 << 16), (u32)l2 | ((u32)l3 << 16));
}

// ---------------------------------------------------------------------------
// Reductions
// ---------------------------------------------------------------------------
__device__ __forceinline__ float block_sum(float v, float* sh) {
#pragma unroll
    for (int o = 16; o > 0; o >>= 1) v += __shfl_xor_sync(0xffffffffu, v, o);
    if ((threadIdx.x & 31) == 0) sh[threadIdx.x >> 5] = v;
    __syncthreads();
    if (threadIdx.x < 32) {
        float w = (threadIdx.x < 8) ? sh[threadIdx.x] : 0.0f;
#pragma unroll
        for (int o = 4; o > 0; o >>= 1) w += __shfl_xor_sync(0xffffffffu, w, o);
        if (threadIdx.x == 0) sh[0] = w;
    }
    __syncthreads();
    float r = sh[0];
    __syncthreads();
    return r;
}
__device__ __forceinline__ float block_max(float v, float* sh) {
#pragma unroll
    for (int o = 16; o > 0; o >>= 1) v = fmaxf(v, __shfl_xor_sync(0xffffffffu, v, o));
    if ((threadIdx.x & 31) == 0) sh[threadIdx.x >> 5] = v;
    __syncthreads();
    if (threadIdx.x < 32) {
        float w = (threadIdx.x < 8) ? sh[threadIdx.x] : -3.4e38f;
#pragma unroll
        for (int o = 4; o > 0; o >>= 1) w = fmaxf(w, __shfl_xor_sync(0xffffffffu, w, o));
        if (threadIdx.x == 0) sh[0] = w;
    }
    __syncthreads();
    float r = sh[0];
    __syncthreads();
    return r;
}

// ---------------------------------------------------------------------------
// LayerNorm emitting split bf16
// ---------------------------------------------------------------------------
__global__ __launch_bounds__(256)
void ln_split(const float* __restrict__ x, u16* __restrict__ yh, u16* __restrict__ yl,
              const float* __restrict__ g, const float* __restrict__ beta)
{
    __shared__ float sh[32];
    const long long row = blockIdx.x;
    const float* xr = x + row * DM;
    const int tid = threadIdx.x;
    float v[4];
    float s = 0.f, sq = 0.f;
#pragma unroll
    for (int i = 0; i < 4; i++) {
        float t = xr[tid + 256 * i];
        v[i] = t; s += t; sq += t * t;
    }
    s  = block_sum(s, sh);
    sq = block_sum(sq, sh);
    float mean = s * (1.0f / 1024.0f);
    float var  = fmaxf(sq * (1.0f / 1024.0f) - mean * mean, 0.0f);
    float inv  = rsqrtf(var + 1e-6f);
#pragma unroll
    for (int i = 0; i < 4; i++) {
        int c = tid + 256 * i;
        float y = (v[i] - mean) * inv * g[c] + beta[c];
        u16 h, l;
        split_bf16(y, h, l);
        yh[row * DM + c] = h;
        yl[row * DM + c] = l;
    }
}

// ---------------------------------------------------------------------------
// GEMM v4: cp.async 3-stage pipeline, pre-split inputs.
// 512 threads, 16 warps (4m x 4n), tile 128 x BN, BK=32.
// TRANSB: B[N,K] rows; else B[K,N] rows staged as [k][n] + ldmatrix.trans.
// ---------------------------------------------------------------------------
template<int BN, bool TRANSB, int ACT, bool EF32, bool ESPL>
__global__ __launch_bounds__(512, 1)
void gemm_cp(const u16* __restrict__ Ahg, const u16* __restrict__ Alg, int lda,
             long long Ab, long long Aho,
             const u16* __restrict__ Bhg, const u16* __restrict__ Blg, int ldb,
             long long Bb, long long Bho,
             float* __restrict__ Cf, u16* __restrict__ Chg, u16* __restrict__ Clg,
             int ldc, long long Cb, long long Cho,
             const float* __restrict__ bias,
             const float* __restrict__ res, int ldr,
             int K, float alpha, int nh)
{
    constexpr int S = 3;
    constexpr int PA = 40;                       // A pitch (halves): 80 B rows
    constexpr int ASZ = 128 * PA;                // 5120
    constexpr int PB = TRANSB ? PA : (BN + 8);   // non-trans: [32][BN+8]
    constexpr int BSZ = TRANSB ? BN * PA : 32 * PB;
    constexpr int STAGE = 2 * ASZ + 2 * BSZ;     // halves
    constexpr int WN = BN / 4;
    constexpr int NT = WN / 8;

    extern __shared__ __align__(128) u16 sm[];

    const int tid = threadIdx.x;
    const int lane = tid & 31;
    const int wid = tid >> 5;
    const int wm = (wid & 3) * 32;
    const int wn = (wid >> 2) * WN;

    const int bz = blockIdx.z;
    const int bb = bz / nh;
    const int hh = bz - bb * nh;
    const int m0 = blockIdx.y * 128;
    const int n0 = blockIdx.x * BN;

    const u16* Ah = Ahg + bb * Ab + hh * Aho + (long long)m0 * lda;
    const u16* Al = Alg + bb * Ab + hh * Aho + (long long)m0 * lda;
    const u16* Bh = Bhg + bb * Bb + hh * Bho + (TRANSB ? (long long)n0 * ldb : (long long)n0);
    const u16* Bl = Blg + bb * Bb + hh * Bho + (TRANSB ? (long long)n0 * ldb : (long long)n0);

    float acc[2][NT][4];
#pragma unroll
    for (int mi = 0; mi < 2; mi++)
#pragma unroll
        for (int ni = 0; ni < NT; ni++)
#pragma unroll
            for (int j = 0; j < 4; j++) acc[mi][ni][j] = 0.0f;

    const u32 sb0 = smem_u32(sm);
    const int nk = K >> 5;

    auto issue = [&](int k) {
        const int slot = k % S;
        const int k0 = k << 5;
        const u32 st = sb0 + (u32)(slot * STAGE) * 2;
        {   // A: 128 rows x 4 chunks of 16B, 1 per thread per array
            const int row = tid >> 2, c = tid & 3;
            const long long o = (long long)row * lda + k0 + c * 8;
            const u32 d = st + (u32)(row * PA + c * 8) * 2;
            CP_ASYNC16(d, (const void*)(Ah + o));
            CP_ASYNC16(d + (u32)ASZ * 2, (const void*)(Al + o));
        }
        if (TRANSB) {
            const int row = tid >> 2, c = tid & 3;
            const long long o = (long long)row * ldb + k0 + c * 8;
            const u32 d = st + (u32)(2 * ASZ + row * PA + c * 8) * 2;
            CP_ASYNC16(d, (const void*)(Bh + o));
            CP_ASYNC16(d + (u32)BSZ * 2, (const void*)(Bl + o));
        } else {
            if (BN == 128 || tid < 256) {
                const int row = (BN == 128) ? (tid >> 4) : (tid >> 3);
                const int c   = (BN == 128) ? (tid & 15) : (tid & 7);
                const long long o = (long long)(k0 + row) * ldb + c * 8;
                const u32 d = st + (u32)(2 * ASZ + row * PB + c * 8) * 2;
                CP_ASYNC16(d, (const void*)(Bh + o));
                CP_ASYNC16(d + (u32)BSZ * 2, (const void*)(Bl + o));
            }
        }
    };

    // prologue: stages 0..S-2
#pragma unroll
    for (int s = 0; s < S - 1; s++) {
        if (s < nk) issue(s);
        CP_COMMIT();
    }

    for (int k = 0; k < nk; k++) {
        CP_WAIT(1);
        __syncthreads();
        if (k + S - 1 < nk) issue(k + S - 1);
        CP_COMMIT();

        const u32 base = sb0 + (u32)((k % S) * STAGE) * 2;
#pragma unroll
        for (int kk = 0; kk < 32; kk += 16) {
            u32 ah[2][4], al_[2][4];
            const int arow = wm + (lane & 15);
            const int acol = kk + ((lane >> 4) << 3);
#pragma unroll
            for (int mi = 0; mi < 2; mi++) {
                u32 ad = base + (u32)(((arow + mi * 16) * PA) + acol) * 2;
                ldsm_x4(ad, ah[mi]);
                ldsm_x4(ad + (u32)ASZ * 2, al_[mi]);
            }
            u32 bh_[NT][2], bl_[NT][2];
            if (TRANSB) {
                const int brow = wn + (lane & 7) + ((lane & 16) >> 1);
                const int bcol = kk + (((lane >> 3) & 1) << 3);
#pragma unroll
                for (int nj = 0; nj < NT / 2; nj++) {
                    u32 bd = base + (u32)(2 * ASZ + (brow + nj * 16) * PA + bcol) * 2;
                    u32 r[4];
                    ldsm_x4(bd, r);
                    bh_[2*nj][0]=r[0]; bh_[2*nj][1]=r[1];
                    bh_[2*nj+1][0]=r[2]; bh_[2*nj+1][1]=r[3];
                    ldsm_x4(bd + (u32)BSZ * 2, r);
                    bl_[2*nj][0]=r[0]; bl_[2*nj][1]=r[1];
                    bl_[2*nj+1][0]=r[2]; bl_[2*nj+1][1]=r[3];
                }
            } else {
                const int brow = kk + (lane & 15);
#pragma unroll
                for (int nj = 0; nj < NT / 2; nj++) {
                    const int bcol = wn + nj * 16 + ((lane >> 4) << 3);
                    u32 bd = base + (u32)(2 * ASZ + brow * PB + bcol) * 2;
                    u32 r[4];
                    ldsm_x4_t(bd, r);
                    bh_[2*nj][0]=r[0]; bh_[2*nj][1]=r[1];
                    bh_[2*nj+1][0]=r[2]; bh_[2*nj+1][1]=r[3];
                    ldsm_x4_t(bd + (u32)BSZ * 2, r);
                    bl_[2*nj][0]=r[0]; bl_[2*nj][1]=r[1];
                    bl_[2*nj+1][0]=r[2]; bl_[2*nj+1][1]=r[3];
                }
            }
#pragma unroll
            for (int mi = 0; mi < 2; mi++)
#pragma unroll
                for (int ni = 0; ni < NT; ni++) {
                    mma_bf16(acc[mi][ni], ah[mi], bh_[ni]);
                    mma_bf16(acc[mi][ni], ah[mi], bl_[ni]);
                    mma_bf16(acc[mi][ni], al_[mi], bh_[ni]);
                }
        }
    }

    // epilogue
    float* Cfg = EF32 ? (Cf + bb * Cb + hh * Cho) : nullptr;
    u16* Chh = ESPL ? (Chg + bb * Cb + hh * Cho) : nullptr;
    u16* Cll = ESPL ? (Clg + bb * Cb + hh * Cho) : nullptr;
#pragma unroll
    for (int mi = 0; mi < 2; mi++) {
#pragma unroll
        for (int ni = 0; ni < NT; ni++) {
            int m = m0 + wm + mi * 16 + (lane >> 2);
            int n = n0 + wn + ni * 8 + (lane & 3) * 2;
#pragma unroll
            for (int rr = 0; rr < 2; rr++) {
                int mm = m + rr * 8;
                float v0 = acc[mi][ni][rr * 2 + 0] * alpha;
                float v1 = acc[mi][ni][rr * 2 + 1] * alpha;
                if (bias) { v0 += bias[n]; v1 += bias[n + 1]; }
                if (ACT == 1) {
                    v0 = 0.5f * v0 * (1.0f + erff(v0 * 0.70710678118654752f));
                    v1 = 0.5f * v1 * (1.0f + erff(v1 * 0.70710678118654752f));
                }
                if (res) {
                    v0 += res[(long long)mm * ldr + n];
                    v1 += res[(long long)mm * ldr + n + 1];
                }
                long long co = (long long)mm * ldc + n;
                if (EF32) *(float2*)(Cfg + co) = make_float2(v0, v1);
                if (ESPL) {
                    *(u32*)(Chh + co) = packhi2(v0, v1);
                    *(u32*)(Cll + co) = packlo2(v0, v1);
                }
            }
        }
    }
}

// ---------------------------------------------------------------------------
// Flash self-attention, cp.async double-buffered K/V.
// 128 threads, 4 warps, 64 q-rows/CTA, 64-key chunks, causal skip.
// ---------------------------------------------------------------------------
__global__ __launch_bounds__(128)
void flash_self(const u16* __restrict__ qh, const u16* __restrict__ ql,
                const unsigned char* __restrict__ kpm,
                u16* __restrict__ ch, u16* __restrict__ cl)
{
    constexpr int P = 72;                 // 144 B rows: 16B aligned, conflict-free
    constexpr int TSZ = 64 * P;           // 4608 halves
    extern __shared__ __align__(128) u16 fs[];
    // layout: Qh(0) Ql(1) | buf0: Kh Kl Vh Vl | buf1: Kh Kl Vh Vl | mask[2][64]
    unsigned char* smask = (unsigned char*)(fs + 10 * TSZ);

    const int tid = threadIdx.x, lane = tid & 31, wid = tid >> 5;
    const int bx = blockIdx.x;
    const int bh = blockIdx.y;
    const int b = bh >> 4, h = bh & 15;
    const int t0 = bx * 64;

    const long long qoff = ((long long)b * TQ + t0) * 3 * DM + h * HD;
    const long long koff = ((long long)b * TQ) * 3 * DM + DM + h * HD;
    const long long voff = ((long long)b * TQ) * 3 * DM + 2 * DM + h * HD;
    const unsigned char* kp = kpm + (long long)b * SK;

    const u32 fsb = smem_u32(fs);

    auto issueKV = [&](int ch_i, int bufi) {
        const int s0 = ch_i * 64;
        const u32 kvb = fsb + (u32)((2 + bufi * 4) * TSZ) * 2;
#pragma unroll
        for (int u = 0; u < 4; u++) {
            int idx = tid + u * 128;
            int r = idx >> 3, c8 = idx & 7;
            long long ko = koff + (long long)(s0 + r) * 3 * DM + c8 * 8;
            long long vo = voff + (long long)(s0 + r) * 3 * DM + c8 * 8;
            u32 d = kvb + (u32)(r * P + c8 * 8) * 2;
            CP_ASYNC16(d,                    (const void*)(qh + ko));
            CP_ASYNC16(d + (u32)TSZ * 2,     (const void*)(ql + ko));
            CP_ASYNC16(d + (u32)TSZ * 4,     (const void*)(qh + vo));
            CP_ASYNC16(d + (u32)TSZ * 6,     (const void*)(ql + vo));
        }
    };

    // Q tile (plain loads) + first K/V chunk
    issueKV(0, 0);
    CP_COMMIT();
#pragma unroll
    for (int u = 0; u < 4; u++) {
        int idx = tid + u * 128;
        int r = idx >> 3, c8 = idx & 7;
        long long o = qoff + (long long)r * 3 * DM + c8 * 8;
        int off = r * P + c8 * 8;
        *(uint4*)(fs + off)       = *(const uint4*)(qh + o);
        *(uint4*)(fs + TSZ + off) = *(const uint4*)(ql + o);
    }
    if (tid < 64) smask[tid] = kp[tid];

    float o_[8][4];
#pragma unroll
    for (int i = 0; i < 8; i++)
#pragma unroll
        for (int j = 0; j < 4; j++) o_[i][j] = 0.0f;
    float mrow0 = -1e30f, mrow1 = -1e30f, lrow0 = 0.0f, lrow1 = 0.0f;

    const int nch = bx + 1;
    int buf = 0;
    for (int ch_i = 0; ch_i < nch; ch_i++) {
        const int s0 = ch_i * 64;
        CP_WAIT(0);
        __syncthreads();
        if (ch_i + 1 < nch) {
            issueKV(ch_i + 1, buf ^ 1);
            if (tid < 64) smask[(buf ^ 1) * 64 + tid] = kp[s0 + 64 + tid];
        }
        CP_COMMIT();

        const u32 kb = fsb + (u32)((2 + buf * 4) * TSZ) * 2;
        const u32 vb = kb + (u32)TSZ * 4;
        const unsigned char* mk = smask + buf * 64;

        // S = 0.125 Q K^T
        float sc[8][4];
#pragma unroll
        for (int i = 0; i < 8; i++)
#pragma unroll
            for (int j = 0; j < 4; j++) sc[i][j] = 0.0f;

#pragma unroll
        for (int kt = 0; kt < 4; kt++) {
            u32 aq[4], al_[4];
            u32 ad = fsb + (u32)(((wid * 16 + (lane & 15)) * P + kt * 16 + ((lane >> 4) << 3))) * 2;
            ldsm_x4(ad, aq);
            ldsm_x4(ad + (u32)TSZ * 2, al_);
            u32 bh_[8][2], bl_[8][2];
#pragma unroll
            for (int nj = 0; nj < 4; nj++) {
                u32 bd = kb + (u32)(((nj * 16 + (lane & 7) + ((lane & 16) >> 1)) * P
                                    + kt * 16 + (((lane >> 3) & 1) << 3))) * 2;
                u32 r[4];
                ldsm_x4(bd, r);
                bh_[2*nj][0]=r[0]; bh_[2*nj][1]=r[1]; bh_[2*nj+1][0]=r[2]; bh_[2*nj+1][1]=r[3];
                ldsm_x4(bd + (u32)TSZ * 2, r);
                bl_[2*nj][0]=r[0]; bl_[2*nj][1]=r[1]; bl_[2*nj+1][0]=r[2]; bl_[2*nj+1][1]=r[3];
            }
#pragma unroll
            for (int ni = 0; ni < 8; ni++) {
                mma_bf16(sc[ni], aq, bh_[ni]);
                mma_bf16(sc[ni], aq, bl_[ni]);
                mma_bf16(sc[ni], al_, bh_[ni]);
            }
        }

        const int gr0 = t0 + wid * 16 + (lane >> 2);
#pragma unroll
        for (int ni = 0; ni < 8; ni++) {
#pragma unroll
            for (int j = 0; j < 4; j++) {
                int rr = gr0 + ((j >> 1) << 3);
                int cl_ = ni * 8 + (lane & 3) * 2 + (j & 1);
                float xv = sc[ni][j] * 0.125f;
                if (s0 + cl_ > rr) xv -= 1e9f;
                if (mk[cl_]) xv = -1e9f;
                sc[ni][j] = xv;
            }
        }

        float mc0 = -1e30f, mc1 = -1e30f;
#pragma unroll
        for (int ni = 0; ni < 8; ni++) {
            mc0 = fmaxf(mc0, fmaxf(sc[ni][0], sc[ni][1]));
            mc1 = fmaxf(mc1, fmaxf(sc[ni][2], sc[ni][3]));
        }
#pragma unroll
        for (int off = 1; off <= 2; off <<= 1) {
            mc0 = fmaxf(mc0, __shfl_xor_sync(0xffffffffu, mc0, off));
            mc1 = fmaxf(mc1, __shfl_xor_sync(0xffffffffu, mc1, off));
        }
        float mn0 = fmaxf(mrow0, mc0), mn1 = fmaxf(mrow1, mc1);
        float scale0 = __expf(mrow0 - mn0), scale1 = __expf(mrow1 - mn1);
        float ls0 = 0.0f, ls1 = 0.0f;
#pragma unroll
        for (int ni = 0; ni < 8; ni++) {
            sc[ni][0] = __expf(sc[ni][0] - mn0);
            sc[ni][1] = __expf(sc[ni][1] - mn0);
            sc[ni][2] = __expf(sc[ni][2] - mn1);
            sc[ni][3] = __expf(sc[ni][3] - mn1);
            ls0 += sc[ni][0] + sc[ni][1];
            ls1 += sc[ni][2] + sc[ni][3];
        }
#pragma unroll
        for (int off = 1; off <= 2; off <<= 1) {
            ls0 += __shfl_xor_sync(0xffffffffu, ls0, off);
            ls1 += __shfl_xor_sync(0xffffffffu, ls1, off);
        }
        lrow0 = lrow0 * scale0 + ls0;
        lrow1 = lrow1 * scale1 + ls1;
        mrow0 = mn0; mrow1 = mn1;
#pragma unroll
        for (int ni = 0; ni < 8; ni++) {
            o_[ni][0] *= scale0; o_[ni][1] *= scale0;
            o_[ni][2] *= scale1; o_[ni][3] *= scale1;
        }

#pragma unroll
        for (int kt = 0; kt < 4; kt++) {
            u32 ph[4], pl[4];
            ph[0] = packhi2(sc[2*kt][0],   sc[2*kt][1]);
            ph[1] = packhi2(sc[2*kt][2],   sc[2*kt][3]);
            ph[2] = packhi2(sc[2*kt+1][0], sc[2*kt+1][1]);
            ph[3] = packhi2(sc[2*kt+1][2], sc[2*kt+1][3]);
            pl[0] = packlo2(sc[2*kt][0],   sc[2*kt][1]);
            pl[1] = packlo2(sc[2*kt][2],   sc[2*kt][3]);
            pl[2] = packlo2(sc[2*kt+1][0], sc[2*kt+1][1]);
            pl[3] = packlo2(sc[2*kt+1][2], sc[2*kt+1][3]);

            u32 vh_[8][2], vl_[8][2];
#pragma unroll
            for (int nj = 0; nj < 4; nj++) {
                u32 bd = vb + (u32)(((kt * 16 + (lane & 15)) * P
                                    + nj * 16 + ((lane >> 4) << 3))) * 2;
                u32 r[4];
                ldsm_x4_t(bd, r);
                vh_[2*nj][0]=r[0]; vh_[2*nj][1]=r[1]; vh_[2*nj+1][0]=r[2]; vh_[2*nj+1][1]=r[3];
                ldsm_x4_t(bd + (u32)TSZ * 2, r);
                vl_[2*nj][0]=r[0]; vl_[2*nj][1]=r[1]; vl_[2*nj+1][0]=r[2]; vl_[2*nj+1][1]=r[3];
            }
#pragma unroll
            for (int ni = 0; ni < 8; ni++) {
                mma_bf16(o_[ni], ph, vh_[ni]);
                mma_bf16(o_[ni], ph, vl_[ni]);
                mma_bf16(o_[ni], pl, vh_[ni]);
            }
        }
        buf ^= 1;
    }

    float inv0 = 1.0f / fmaxf(lrow0, 1e-30f);
    float inv1 = 1.0f / fmaxf(lrow1, 1e-30f);
    const long long cbase = ((long long)b * TQ) * DM + h * HD;
    const int r0 = t0 + wid * 16 + (lane >> 2);
#pragma unroll
    for (int ni = 0; ni < 8; ni++) {
        int c = ni * 8 + (lane & 3) * 2;
        long long o0 = cbase + (long long)r0 * DM + c;
        long long o1 = cbase + (long long)(r0 + 8) * DM + c;
        *(u32*)(ch + o0) = packhi2(o_[ni][0] * inv0, o_[ni][1] * inv0);
        *(u32*)(cl + o0) = packlo2(o_[ni][0] * inv0, o_[ni][1] * inv0);
        *(u32*)(ch + o1) = packhi2(o_[ni][2] * inv1, o_[ni][3] * inv1);
        *(u32*)(cl + o1) = packlo2(o_[ni][2] * inv1, o_[ni][3] * inv1);
    }
}

// ---------------------------------------------------------------------------
// Fused cross softmax (contiguous per-thread layout)
// ---------------------------------------------------------------------------
__global__ __launch_bounds__(256)
void softmax_fused(const float* __restrict__ sc, const unsigned char* __restrict__ kpm,
                   const float* __restrict__ tvn,
                   u16* __restrict__ ph, u16* __restrict__ pl, float* __restrict__ out2)
{
    __shared__ float sh[32];
    __shared__ unsigned char km[SK];
    const int t = blockIdx.x, b = blockIdx.y;
    const int tid = threadIdx.x;
    const int s0 = tid * 4;
    for (int i = tid; i < SK; i += 256) km[i] = kpm[(long long)b * SK + i];
    __syncthreads();

    float psum[4] = {0.f, 0.f, 0.f, 0.f};
    for (int h = 0; h < HH; h++) {
        const long long roff = (((long long)(b * HH + h)) * TQ + t) * SK;
        float4 v4 = *(const float4*)(sc + roff + s0);
        float v[4] = {v4.x, v4.y, v4.z, v4.w};
        float mx = -3.4e38f;
#pragma unroll
        for (int i = 0; i < 4; i++) {
            if (km[s0 + i]) v[i] = -1e9f;
            mx = fmaxf(mx, v[i]);
        }
        mx = block_max(mx, sh);
        float sum = 0.f;
#pragma unroll
        for (int i = 0; i < 4; i++) {
            v[i] = __expf(v[i] - mx);
            sum += v[i];
        }
        sum = block_sum(sum, sh);
        float inv = 1.0f / sum;
#pragma unroll
        for (int i = 0; i < 4; i++) {
            v[i] *= inv;
            psum[i] += v[i];
        }
        *(uint2*)(ph + roff + s0) = make_uint2(packhi2(v[0], v[1]), packhi2(v[2], v[3]));
        *(uint2*)(pl + roff + s0) = make_uint2(packlo2(v[0], v[1]), packlo2(v[2], v[3]));
    }
    float4 tv4 = *(const float4*)(tvn + b * SK + s0);
    float4 o4 = make_float4(psum[0] * (1.0f/16.0f) * tv4.x, psum[1] * (1.0f/16.0f) * tv4.y,
                            psum[2] * (1.0f/16.0f) * tv4.z, psum[3] * (1.0f/16.0f) * tv4.w);
    *(float4*)(out2 + ((long long)b * TQ + t) * SK + s0) = o4;
}

// ---------------------------------------------------------------------------
// Row L2 norm
// ---------------------------------------------------------------------------
__global__ __launch_bounds__(256)
void rownorm_kernel(const float* __restrict__ x, float* __restrict__ out)
{
    __shared__ float sh[32];
    const long long row = blockIdx.x;
    const float* xr = x + row * DM;
    float sq = 0.f;
#pragma unroll
    for (int i = 0; i < 4; i++) {
        float t = xr[threadIdx.x + 256 * i];
        sq += t * t;
    }
    sq = block_sum(sq, sh);
    if (threadIdx.x == 0) out[row] = sqrtf(sq);
}

// ---------------------------------------------------------------------------
// Host launcher
// ---------------------------------------------------------------------------
extern "C" void kernel_launch(void* const* d_in, const int* in_sizes, int n_in,
                              void* d_out, int out_size)
{
    const float* dec_in  = (const float*)d_in[0];
    const float* enc_out = (const float*)d_in[1];
    const unsigned char* en_mask = (const unsigned char*)d_in[2];
    const unsigned char* de_mask = (const unsigned char*)d_in[3];
    const float* ln_g   = (const float*)d_in[4];
    const float* ln_b   = (const float*)d_in[5];
    const float* w_in1  = (const float*)d_in[6];
    const float* b_in1  = (const float*)d_in[7];
    const float* w_out1 = (const float*)d_in[8];
    const float* b_out1 = (const float*)d_in[9];
    const float* w_in2  = (const float*)d_in[10];
    const float* b_in2  = (const float*)d_in[11];
    const float* w_out2 = (const float*)d_in[12];
    const float* b_out2 = (const float*)d_in[13];
    const float* mlp_w1 = (const float*)d_in[14];
    const float* mlp_b1 = (const float*)d_in[15];
    const float* mlp_w2 = (const float*)d_in[16];
    const float* mlp_b2 = (const float*)d_in[17];

    float *scores, *x, *x2, *tv, *tvn;
    cudaGetSymbolAddress((void**)&scores, g_scores);
    cudaGetSymbolAddress((void**)&x,  g_x);
    cudaGetSymbolAddress((void**)&x2, g_x2);
    cudaGetSymbolAddress((void**)&tv, g_tv);
    cudaGetSymbolAddress((void**)&tvn, g_tvn);

    u16 *deh,*del,*enh,*enl,*qkvh,*qkvl,*ctxh,*ctxl,*xh,*xl,*q2h,*q2l,*kv2h,*kv2l;
    u16 *lnxh,*lnxl,*hhp,*hlp,*ph,*pl;
    u16 *w1h,*w1l,*wo1h,*wo1l,*w2h,*w2l,*wo2h,*wo2l,*m1h,*m1l,*m2h,*m2l;
    cudaGetSymbolAddress((void**)&deh, g_deh);   cudaGetSymbolAddress((void**)&del, g_del);
    cudaGetSymbolAddress((void**)&enh, g_enh);   cudaGetSymbolAddress((void**)&enl, g_enl);
    cudaGetSymbolAddress((void**)&qkvh, g_qkvh); cudaGetSymbolAddress((void**)&qkvl, g_qkvl);
    cudaGetSymbolAddress((void**)&ctxh, g_ctxh); cudaGetSymbolAddress((void**)&ctxl, g_ctxl);
    cudaGetSymbolAddress((void**)&xh, g_xh);     cudaGetSymbolAddress((void**)&xl, g_xl);
    cudaGetSymbolAddress((void**)&q2h, g_q2h);   cudaGetSymbolAddress((void**)&q2l, g_q2l);
    cudaGetSymbolAddress((void**)&kv2h, g_kv2h); cudaGetSymbolAddress((void**)&kv2l, g_kv2l);
    cudaGetSymbolAddress((void**)&lnxh, g_lnxh); cudaGetSymbolAddress((void**)&lnxl, g_lnxl);
    cudaGetSymbolAddress((void**)&hhp, g_hh);    cudaGetSymbolAddress((void**)&hlp, g_hl);
    cudaGetSymbolAddress((void**)&ph, g_ph);     cudaGetSymbolAddress((void**)&pl, g_pl);
    cudaGetSymbolAddress((void**)&w1h, g_w1h);   cudaGetSymbolAddress((void**)&w1l, g_w1l);
    cudaGetSymbolAddress((void**)&wo1h, g_wo1h); cudaGetSymbolAddress((void**)&wo1l, g_wo1l);
    cudaGetSymbolAddress((void**)&w2h, g_w2h);   cudaGetSymbolAddress((void**)&w2l, g_w2l);
    cudaGetSymbolAddress((void**)&wo2h, g_wo2h); cudaGetSymbolAddress((void**)&wo2l, g_wo2l);
    cudaGetSymbolAddress((void**)&m1h, g_m1h);   cudaGetSymbolAddress((void**)&m1l, g_m1l);
    cudaGetSymbolAddress((void**)&m2h, g_m2h);   cudaGetSymbolAddress((void**)&m2l, g_m2l);

    float* out1 = (float*)d_out;
    float* out2 = (float*)d_out + (long long)BZ * TQ * DM;

    const int BT = BZ * TQ;
    const long long TSh = (long long)TQ * SK;
    const long long TSb = (long long)HH * TQ * SK;

    // smem sizes (bytes): 3 stages
    const int SM_T128  = 3 * (2 * 128 * 40 + 2 * 128 * 40) * 2;   // 122880
    const int SM_NT128 = 3 * (2 * 128 * 40 + 2 * 32 * 136) * 2;   // 113664
    const int SM_NT64  = 3 * (2 * 128 * 40 + 2 * 32 * 72) * 2;    //  89088
    const int SMFL     = 10 * 64 * 72 * 2 + 128;                  //  92288
    cudaFuncSetAttribute(gemm_cp<128,true ,0,false,true >, cudaFuncAttributeMaxDynamicSharedMemorySize, SM_T128);
    cudaFuncSetAttribute(gemm_cp<128,true ,0,true ,true >, cudaFuncAttributeMaxDynamicSharedMemorySize, SM_T128);
    cudaFuncSetAttribute(gemm_cp<128,true ,0,true ,false>, cudaFuncAttributeMaxDynamicSharedMemorySize, SM_T128);
    cudaFuncSetAttribute(gemm_cp<128,false,0,true ,false>, cudaFuncAttributeMaxDynamicSharedMemorySize, SM_NT128);
    cudaFuncSetAttribute(gemm_cp<64 ,false,0,false,true >, cudaFuncAttributeMaxDynamicSharedMemorySize, SM_NT64);
    cudaFuncSetAttribute(gemm_cp<128,true ,1,false,true >, cudaFuncAttributeMaxDynamicSharedMemorySize, SM_T128);
    cudaFuncSetAttribute(flash_self, cudaFuncAttributeMaxDynamicSharedMemorySize, SMFL);

    // 0: split weights
    split_kernel<<<(3*DM*DM/4 + 255)/256, 256>>>(w_in1,  w1h,  w1l,  3*DM*DM/4);
    split_kernel<<<(DM*DM/4   + 255)/256, 256>>>(w_out1, wo1h, wo1l, DM*DM/4);
    split_kernel<<<(3*DM*DM/4 + 255)/256, 256>>>(w_in2,  w2h,  w2l,  3*DM*DM/4);
    split_kernel<<<(DM*DM/4   + 255)/256, 256>>>(w_out2, wo2h, wo2l, DM*DM/4);
    split_kernel<<<(4*DM*DM/4 + 255)/256, 256>>>(mlp_w1, m1h,  m1l,  4*DM*DM/4);
    split_kernel<<<(4*DM*DM/4 + 255)/256, 256>>>(mlp_w2, m2h,  m2l,  4*DM*DM/4);

    // 1-2: LayerNorms -> split
    ln_split<<<BT, 256>>>(dec_in, deh, del, ln_g, ln_b);
    ln_split<<<BT, 256>>>(enc_out, enh, enl, ln_g, ln_b);

    // 3: QKV1 -> split
    gemm_cp<128,true,0,false,true><<<dim3(3*DM/128, BT/128, 1), 512, SM_T128>>>(
        deh, del, DM, 0, 0,  w1h, w1l, DM, 0, 0,
        nullptr, qkvh, qkvl, 3*DM, 0, 0,
        b_in1, nullptr, 0, DM, 1.0f, 1);

    // 4: flash self-attention -> ctx split
    flash_self<<<dim3(TQ/64, BZ*HH), 128, SMFL>>>(qkvh, qkvl, de_mask, ctxh, ctxl);

    // 5: x = dec_in + ctx @ w_out1^T + b_out1 (fp32 + split)
    gemm_cp<128,true,0,true,true><<<dim3(DM/128, BT/128, 1), 512, SM_T128>>>(
        ctxh, ctxl, DM, 0, 0,  wo1h, wo1l, DM, 0, 0,
        x, xh, xl, DM, 0, 0,
        b_out1, dec_in, DM, DM, 1.0f, 1);

    // 6: q2 -> split
    gemm_cp<128,true,0,false,true><<<dim3(DM/128, BT/128, 1), 512, SM_T128>>>(
        xh, xl, DM, 0, 0,  w2h, w2l, DM, 0, 0,
        nullptr, q2h, q2l, DM, 0, 0,
        b_in2, nullptr, 0, DM, 1.0f, 1);

    // 7: kv2 -> split
    gemm_cp<128,true,0,false,true><<<dim3(2*DM/128, BT/128, 1), 512, SM_T128>>>(
        enh, enl, DM, 0, 0,  w2h + (long long)DM*DM, w2l + (long long)DM*DM, DM, 0, 0,
        nullptr, kv2h, kv2l, 2*DM, 0, 0,
        b_in2 + DM, nullptr, 0, DM, 1.0f, 1);

    // 8: tv = en_out @ w_out2 (non-trans) -> fp32 ; 9: rownorm
    gemm_cp<128,false,0,true,false><<<dim3(DM/128, BT/128, 1), 512, SM_NT128>>>(
        enh, enl, DM, 0, 0,  wo2h, wo2l, DM, 0, 0,
        tv, nullptr, nullptr, DM, 0, 0,
        nullptr, nullptr, 0, DM, 1.0f, 1);
    rownorm_kernel<<<BT, 256>>>(tv, tvn);

    // 10: cross scores -> fp32
    gemm_cp<128,true,0,true,false><<<dim3(SK/128, TQ/128, BZ*HH), 512, SM_T128>>>(
        q2h, q2l, DM, (long long)TQ*DM, HD,
        kv2h, kv2l, 2*DM, (long long)SK*2*DM, HD,
        scores, nullptr, nullptr, SK, TSb, TSh,
        nullptr, nullptr, 0, HD, 0.125f, HH);

    // 11: fused softmax: probs split + out2
    softmax_fused<<<dim3(TQ, BZ), 256>>>(scores, en_mask, tvn, ph, pl, out2);

    // 12: ctx = probs @ V2 -> split
    gemm_cp<64,false,0,false,true><<<dim3(1, TQ/128, BZ*HH), 512, SM_NT64>>>(
        ph, pl, SK, TSb, TSh,
        kv2h + DM, kv2l + DM, 2*DM, (long long)SK*2*DM, HD,
        nullptr, ctxh, ctxl, DM, (long long)TQ*DM, HD,
        nullptr, nullptr, 0, SK, 1.0f, HH);

    // 13: x2 = x + ctx @ w_out2^T + b_out2 -> fp32
    gemm_cp<128,true,0,true,false><<<dim3(DM/128, BT/128, 1), 512, SM_T128>>>(
        ctxh, ctxl, DM, 0, 0,  wo2h, wo2l, DM, 0, 0,
        x2, nullptr, nullptr, DM, 0, 0,
        b_out2, x, DM, DM, 1.0f, 1);

    // 14: lnx -> split
    ln_split<<<BT, 256>>>(x2, lnxh, lnxl, ln_g, ln_b);

    // 15: h = gelu(lnx @ mlp_w1^T + b1) -> split
    gemm_cp<128,true,1,false,true><<<dim3(4*DM/128, BT/128, 1), 512, SM_T128>>>(
        lnxh, lnxl, DM, 0, 0,  m1h, m1l, DM, 0, 0,
        nullptr, hhp, hlp, 4*DM, 0, 0,
        mlp_b1, nullptr, 0, DM, 1.0f, 1);

    // 16: out1 = x2 + h @ mlp_w2^T + b2
    gemm_cp<128,true,0,true,false><<<dim3(DM/128, BT/128, 1), 512, SM_T128>>>(
        hhp, hlp, 4*DM, 0, 0,  m2h, m2l, 4*DM, 0, 0,
        out1, nullptr, nullptr, DM, 0, 0,
        mlp_b2, x2, DM, 4*DM, 1.0f, 1);
}